// round 1
// baseline (speedup 1.0000x reference)
#include <cuda_runtime.h>
#include <cuda_bf16.h>

// Problem dims (fixed): B=4, S=4096, D=2048, Db=512
#define T_ROWS 16384
#define DIM    2048
#define DBOT   512
#define LN_EPS 1e-5f

// GEMM tiling
#define BM 128
#define BN 128
#define BK 32
#define BKP 40   // padded k-stride in bf16 elements (80 bytes -> conflict-free frag loads)

// Scratch (no allocation allowed -> __device__ globals)
__device__ float g_mu[T_ROWS];
__device__ float g_rstd[T_ROWS];
__device__ __nv_bfloat16 g_z[(size_t)T_ROWS * DBOT];   // 16 MB

// ---------------------------------------------------------------------------
// Kernel 0: per-row LayerNorm statistics (mean, rstd). One warp per row.
// ---------------------------------------------------------------------------
__global__ void ln_stats_kernel(const float* __restrict__ hidden) {
    int row = blockIdx.x * blockDim.y + threadIdx.y;
    const float4* hp = reinterpret_cast<const float4*>(hidden + (size_t)row * DIM);
    float s = 0.f, ss = 0.f;
    for (int i = threadIdx.x; i < DIM / 4; i += 32) {
        float4 v = hp[i];
        s  += v.x + v.y + v.z + v.w;
        ss += v.x * v.x + v.y * v.y + v.z * v.z + v.w * v.w;
    }
#pragma unroll
    for (int o = 16; o > 0; o >>= 1) {
        s  += __shfl_xor_sync(0xffffffffu, s, o);
        ss += __shfl_xor_sync(0xffffffffu, ss, o);
    }
    if (threadIdx.x == 0) {
        float mu  = s * (1.f / DIM);
        float var = ss * (1.f / DIM) - mu * mu;
        g_mu[row]   = mu;
        g_rstd[row] = rsqrtf(var + LN_EPS);
    }
}

// ---------------------------------------------------------------------------
// mma.sync m16n8k16 bf16 (fp32 accumulate), accumulate in place
// ---------------------------------------------------------------------------
__device__ __forceinline__ void mma16816(float c[4], const unsigned a[4], const unsigned b[2]) {
    asm volatile(
        "mma.sync.aligned.m16n8k16.row.col.f32.bf16.bf16.f32 "
        "{%0,%1,%2,%3}, {%4,%5,%6,%7}, {%8,%9}, {%0,%1,%2,%3};\n"
        : "+f"(c[0]), "+f"(c[1]), "+f"(c[2]), "+f"(c[3])
        : "r"(a[0]), "r"(a[1]), "r"(a[2]), "r"(a[3]), "r"(b[0]), "r"(b[1]));
}

__device__ __forceinline__ float silu(float v) {
    return v * (1.f / (1.f + __expf(-v)));
}

// ---------------------------------------------------------------------------
// Kernel 1: z = SiLU( LN(hidden) @ W_down + b_down )  -> g_z (bf16)
// A tile: normalize-on-load from fp32 hidden using g_mu/g_rstd.
// ---------------------------------------------------------------------------
__global__ __launch_bounds__(256, 2) void gemm1_kernel(
    const float* __restrict__ hidden,
    const float* __restrict__ gamma,
    const float* __restrict__ beta,
    const float* __restrict__ Wd,
    const float* __restrict__ bd)
{
    __shared__ __align__(16) __nv_bfloat16 As[BM * BKP];
    __shared__ __align__(16) __nv_bfloat16 Bs[BN * BKP];

    const int tid   = threadIdx.x;
    const int warp  = tid >> 5;
    const int lane  = tid & 31;
    const int wm    = warp >> 2;     // 0..1  (64-row slab)
    const int wn    = warp & 3;      // 0..3  (32-col slab)
    const int group = lane >> 2;     // 0..7
    const int tg    = lane & 3;      // 0..3

    const int rowBase = blockIdx.y * BM;
    const int n0      = blockIdx.x * BN;

    float c[4][4][4];
#pragma unroll
    for (int i = 0; i < 4; i++)
#pragma unroll
        for (int j = 0; j < 4; j++)
#pragma unroll
            for (int k = 0; k < 4; k++) c[i][j][k] = 0.f;

    // A-load indexing: 128 rows x 32 k, float4 per thread, 4 passes
    const int arow = tid >> 3;        // 0..31
    const int acol = (tid & 7) * 4;   // 0..28
    // B-load indexing: 32 k-rows x 128 n, float4 along n, 4 passes
    const int bkrow = tid >> 5;       // 0..7
    const int bncol = (tid & 31) * 4; // 0..124

    for (int k0 = 0; k0 < DIM; k0 += BK) {
        // ---- load + normalize A tile -> bf16 smem ----
        float4 gg = *reinterpret_cast<const float4*>(gamma + k0 + acol);
        float4 bb = *reinterpret_cast<const float4*>(beta  + k0 + acol);
#pragma unroll
        for (int p = 0; p < 4; ++p) {
            int r  = arow + p * 32;
            int gr = rowBase + r;
            float4 v = *reinterpret_cast<const float4*>(hidden + (size_t)gr * DIM + k0 + acol);
            float mu = g_mu[gr], rs = g_rstd[gr];
            float n0v = (v.x - mu) * rs * gg.x + bb.x;
            float n1v = (v.y - mu) * rs * gg.y + bb.y;
            float n2v = (v.z - mu) * rs * gg.z + bb.z;
            float n3v = (v.w - mu) * rs * gg.w + bb.w;
            __nv_bfloat162* dst = reinterpret_cast<__nv_bfloat162*>(&As[r * BKP + acol]);
            dst[0] = __floats2bfloat162_rn(n0v, n1v);
            dst[1] = __floats2bfloat162_rn(n2v, n3v);
        }
        // ---- load B tile (W_down[k][n]) transposed -> Bs[n][k] bf16 ----
#pragma unroll
        for (int p = 0; p < 4; ++p) {
            int kk = bkrow + p * 8;
            float4 w = *reinterpret_cast<const float4*>(Wd + (size_t)(k0 + kk) * DBOT + n0 + bncol);
            Bs[(bncol + 0) * BKP + kk] = __float2bfloat16_rn(w.x);
            Bs[(bncol + 1) * BKP + kk] = __float2bfloat16_rn(w.y);
            Bs[(bncol + 2) * BKP + kk] = __float2bfloat16_rn(w.z);
            Bs[(bncol + 3) * BKP + kk] = __float2bfloat16_rn(w.w);
        }
        __syncthreads();

#pragma unroll
        for (int kk = 0; kk < BK; kk += 16) {
            unsigned a[4][4], b[4][2];
#pragma unroll
            for (int mi = 0; mi < 4; ++mi) {
                int mr = wm * 64 + mi * 16 + group;
                a[mi][0] = *reinterpret_cast<const unsigned*>(&As[mr * BKP + kk + tg * 2]);
                a[mi][1] = *reinterpret_cast<const unsigned*>(&As[(mr + 8) * BKP + kk + tg * 2]);
                a[mi][2] = *reinterpret_cast<const unsigned*>(&As[mr * BKP + kk + tg * 2 + 8]);
                a[mi][3] = *reinterpret_cast<const unsigned*>(&As[(mr + 8) * BKP + kk + tg * 2 + 8]);
            }
#pragma unroll
            for (int ni = 0; ni < 4; ++ni) {
                int nc = wn * 32 + ni * 8 + group;
                b[ni][0] = *reinterpret_cast<const unsigned*>(&Bs[nc * BKP + kk + tg * 2]);
                b[ni][1] = *reinterpret_cast<const unsigned*>(&Bs[nc * BKP + kk + tg * 2 + 8]);
            }
#pragma unroll
            for (int mi = 0; mi < 4; ++mi)
#pragma unroll
                for (int ni = 0; ni < 4; ++ni)
                    mma16816(c[mi][ni], a[mi], b[ni]);
        }
        __syncthreads();
    }

    // ---- epilogue: +b_down, SiLU, store bf16 z ----
#pragma unroll
    for (int mi = 0; mi < 4; ++mi) {
        int r0 = rowBase + wm * 64 + mi * 16 + group;
#pragma unroll
        for (int ni = 0; ni < 4; ++ni) {
            int cc  = n0 + wn * 32 + ni * 8 + tg * 2;
            float bd0 = bd[cc], bd1 = bd[cc + 1];
            float v0 = silu(c[mi][ni][0] + bd0);
            float v1 = silu(c[mi][ni][1] + bd1);
            float v2 = silu(c[mi][ni][2] + bd0);
            float v3 = silu(c[mi][ni][3] + bd1);
            *reinterpret_cast<__nv_bfloat162*>(&g_z[(size_t)r0 * DBOT + cc]) =
                __floats2bfloat162_rn(v0, v1);
            *reinterpret_cast<__nv_bfloat162*>(&g_z[(size_t)(r0 + 8) * DBOT + cc]) =
                __floats2bfloat162_rn(v2, v3);
        }
    }
}

// ---------------------------------------------------------------------------
// Kernel 2: out = hidden + alpha * ( z @ W_up + b_up - hidden )
// ---------------------------------------------------------------------------
__global__ __launch_bounds__(256, 2) void gemm2_kernel(
    const float* __restrict__ hidden,
    const float* __restrict__ Wu,
    const float* __restrict__ bu,
    const float* __restrict__ alpha_p,
    float* __restrict__ out)
{
    __shared__ __align__(16) __nv_bfloat16 As[BM * BKP];
    __shared__ __align__(16) __nv_bfloat16 Bs[BN * BKP];

    const int tid   = threadIdx.x;
    const int warp  = tid >> 5;
    const int lane  = tid & 31;
    const int wm    = warp >> 2;
    const int wn    = warp & 3;
    const int group = lane >> 2;
    const int tg    = lane & 3;

    const int rowBase = blockIdx.y * BM;
    const int n0      = blockIdx.x * BN;

    float c[4][4][4];
#pragma unroll
    for (int i = 0; i < 4; i++)
#pragma unroll
        for (int j = 0; j < 4; j++)
#pragma unroll
            for (int k = 0; k < 4; k++) c[i][j][k] = 0.f;

    // A-load: 128 rows x 32 k of bf16 z, uint4 (8 bf16) per thread, 2 passes
    const int arow = tid >> 2;        // 0..63
    const int acol = (tid & 3) * 8;   // 0..24
    // B-load: same as gemm1 but row stride DIM
    const int bkrow = tid >> 5;
    const int bncol = (tid & 31) * 4;

    for (int k0 = 0; k0 < DBOT; k0 += BK) {
#pragma unroll
        for (int p = 0; p < 2; ++p) {
            int r = arow + p * 64;
            uint4 v = *reinterpret_cast<const uint4*>(&g_z[(size_t)(rowBase + r) * DBOT + k0 + acol]);
            *reinterpret_cast<uint4*>(&As[r * BKP + acol]) = v;
        }
#pragma unroll
        for (int p = 0; p < 4; ++p) {
            int kk = bkrow + p * 8;
            float4 w = *reinterpret_cast<const float4*>(Wu + (size_t)(k0 + kk) * DIM + n0 + bncol);
            Bs[(bncol + 0) * BKP + kk] = __float2bfloat16_rn(w.x);
            Bs[(bncol + 1) * BKP + kk] = __float2bfloat16_rn(w.y);
            Bs[(bncol + 2) * BKP + kk] = __float2bfloat16_rn(w.z);
            Bs[(bncol + 3) * BKP + kk] = __float2bfloat16_rn(w.w);
        }
        __syncthreads();

#pragma unroll
        for (int kk = 0; kk < BK; kk += 16) {
            unsigned a[4][4], b[4][2];
#pragma unroll
            for (int mi = 0; mi < 4; ++mi) {
                int mr = wm * 64 + mi * 16 + group;
                a[mi][0] = *reinterpret_cast<const unsigned*>(&As[mr * BKP + kk + tg * 2]);
                a[mi][1] = *reinterpret_cast<const unsigned*>(&As[(mr + 8) * BKP + kk + tg * 2]);
                a[mi][2] = *reinterpret_cast<const unsigned*>(&As[mr * BKP + kk + tg * 2 + 8]);
                a[mi][3] = *reinterpret_cast<const unsigned*>(&As[(mr + 8) * BKP + kk + tg * 2 + 8]);
            }
#pragma unroll
            for (int ni = 0; ni < 4; ++ni) {
                int nc = wn * 32 + ni * 8 + group;
                b[ni][0] = *reinterpret_cast<const unsigned*>(&Bs[nc * BKP + kk + tg * 2]);
                b[ni][1] = *reinterpret_cast<const unsigned*>(&Bs[nc * BKP + kk + tg * 2 + 8]);
            }
#pragma unroll
            for (int mi = 0; mi < 4; ++mi)
#pragma unroll
                for (int ni = 0; ni < 4; ++ni)
                    mma16816(c[mi][ni], a[mi], b[ni]);
        }
        __syncthreads();
    }

    // ---- epilogue: +b_up, alpha-gated residual ----
    const float al = alpha_p[0];
#pragma unroll
    for (int mi = 0; mi < 4; ++mi) {
        int r0 = rowBase + wm * 64 + mi * 16 + group;
        int r1 = r0 + 8;
#pragma unroll
        for (int ni = 0; ni < 4; ++ni) {
            int cc  = n0 + wn * 32 + ni * 8 + tg * 2;
            float bu0 = bu[cc], bu1 = bu[cc + 1];

            float2 h0 = *reinterpret_cast<const float2*>(hidden + (size_t)r0 * DIM + cc);
            float2 h1 = *reinterpret_cast<const float2*>(hidden + (size_t)r1 * DIM + cc);

            float2 o0, o1;
            o0.x = h0.x + al * (c[mi][ni][0] + bu0 - h0.x);
            o0.y = h0.y + al * (c[mi][ni][1] + bu1 - h0.y);
            o1.x = h1.x + al * (c[mi][ni][2] + bu0 - h1.x);
            o1.y = h1.y + al * (c[mi][ni][3] + bu1 - h1.y);

            *reinterpret_cast<float2*>(out + (size_t)r0 * DIM + cc) = o0;
            *reinterpret_cast<float2*>(out + (size_t)r1 * DIM + cc) = o1;
        }
    }
}

// ---------------------------------------------------------------------------
// Launch
// ---------------------------------------------------------------------------
extern "C" void kernel_launch(void* const* d_in, const int* in_sizes, int n_in,
                              void* d_out, int out_size) {
    const float* hidden = (const float*)d_in[0];
    const float* gamma  = (const float*)d_in[1];
    const float* beta   = (const float*)d_in[2];
    const float* Wd     = (const float*)d_in[3];
    const float* bd     = (const float*)d_in[4];
    const float* Wu     = (const float*)d_in[5];
    const float* bu     = (const float*)d_in[6];
    const float* alpha  = (const float*)d_in[7];
    float* out = (float*)d_out;

    ln_stats_kernel<<<T_ROWS / 8, dim3(32, 8)>>>(hidden);
    gemm1_kernel<<<dim3(DBOT / BN, T_ROWS / BM), 256>>>(hidden, gamma, beta, Wd, bd);
    gemm2_kernel<<<dim3(DIM / BN, T_ROWS / BM), 256>>>(hidden, Wu, bu, alpha, out);
}

// round 5
// speedup vs baseline: 2.8112x; 2.8112x over previous
#include <cuda_runtime.h>
#include <cuda_bf16.h>

// Problem dims (fixed): B=4, S=4096, D=2048, Db=512
#define T_ROWS 16384
#define DIM    2048
#define DBOT   512
#define LN_EPS 1e-5f

// GEMM tiling
#define BM 128
#define BN 128
#define BK 32
#define BKP 40       // padded k-stride (80B rows): ldmatrix + cp.async conflict-free
#define STAGES 2     // ping-pong (keeps static smem under 48KB)

// ---------------------------------------------------------------------------
// Device scratch (allocation is forbidden -> __device__ globals)
// ---------------------------------------------------------------------------
__device__ __nv_bfloat16 g_hn[(size_t)T_ROWS * DIM];   // 64 MB normalized hidden (bf16)
__device__ __nv_bfloat16 g_z[(size_t)T_ROWS * DBOT];   // 16 MB bottleneck activations
__device__ __nv_bfloat16 g_WdT[(size_t)DBOT * DIM];    // W_down^T bf16  [n][k]
__device__ __nv_bfloat16 g_WuT[(size_t)DIM * DBOT];    // W_up^T   bf16  [n][k]

// ---------------------------------------------------------------------------
// PTX helpers
// ---------------------------------------------------------------------------
__device__ __forceinline__ unsigned smem_u32(const void* p) {
    return (unsigned)__cvta_generic_to_shared(p);
}
__device__ __forceinline__ void cpa16(unsigned dst, const void* src) {
    asm volatile("cp.async.cg.shared.global [%0], [%1], 16;\n" :: "r"(dst), "l"(src));
}
__device__ __forceinline__ void cpa_commit() {
    asm volatile("cp.async.commit_group;\n");
}
template <int N>
__device__ __forceinline__ void cpa_wait() {
    asm volatile("cp.async.wait_group %0;\n" :: "n"(N));
}
__device__ __forceinline__ void ldsm_x4(unsigned& r0, unsigned& r1, unsigned& r2, unsigned& r3,
                                        unsigned addr) {
    asm volatile("ldmatrix.sync.aligned.m8n8.x4.shared.b16 {%0,%1,%2,%3}, [%4];\n"
                 : "=r"(r0), "=r"(r1), "=r"(r2), "=r"(r3) : "r"(addr));
}
__device__ __forceinline__ void mma16816(float c[4], const unsigned a[4], const unsigned b[2]) {
    asm volatile(
        "mma.sync.aligned.m16n8k16.row.col.f32.bf16.bf16.f32 "
        "{%0,%1,%2,%3}, {%4,%5,%6,%7}, {%8,%9}, {%0,%1,%2,%3};\n"
        : "+f"(c[0]), "+f"(c[1]), "+f"(c[2]), "+f"(c[3])
        : "r"(a[0]), "r"(a[1]), "r"(a[2]), "r"(a[3]), "r"(b[0]), "r"(b[1]));
}
__device__ __forceinline__ float silu(float v) {
    return v * (1.f / (1.f + __expf(-v)));
}
__device__ __forceinline__ uint2 pack4(float a, float b, float c, float d) {
    __nv_bfloat162 p0 = __floats2bfloat162_rn(a, b);
    __nv_bfloat162 p1 = __floats2bfloat162_rn(c, d);
    uint2 u;
    u.x = *reinterpret_cast<unsigned*>(&p0);
    u.y = *reinterpret_cast<unsigned*>(&p1);
    return u;
}

// ---------------------------------------------------------------------------
// Kernel: fused LayerNorm -> bf16 h_norm (one block per row, read+write once)
// ---------------------------------------------------------------------------
__global__ __launch_bounds__(256) void ln_norm_kernel(
    const float* __restrict__ hidden,
    const float* __restrict__ gamma,
    const float* __restrict__ beta)
{
    const int row = blockIdx.x;
    const int t = threadIdx.x;
    const int warp = t >> 5, lane = t & 31;

    const float4* hp = reinterpret_cast<const float4*>(hidden + (size_t)row * DIM);
    float4 v0 = hp[t], v1 = hp[t + 256];

    float s  = v0.x + v0.y + v0.z + v0.w + v1.x + v1.y + v1.z + v1.w;
    float ss = v0.x * v0.x + v0.y * v0.y + v0.z * v0.z + v0.w * v0.w
             + v1.x * v1.x + v1.y * v1.y + v1.z * v1.z + v1.w * v1.w;
#pragma unroll
    for (int o = 16; o > 0; o >>= 1) {
        s  += __shfl_xor_sync(0xffffffffu, s, o);
        ss += __shfl_xor_sync(0xffffffffu, ss, o);
    }
    __shared__ float rs[8], rss[8], stats[2];
    if (lane == 0) { rs[warp] = s; rss[warp] = ss; }
    __syncthreads();
    if (warp == 0) {
        float s2  = (lane < 8) ? rs[lane]  : 0.f;
        float ss2 = (lane < 8) ? rss[lane] : 0.f;
#pragma unroll
        for (int o = 4; o > 0; o >>= 1) {
            s2  += __shfl_xor_sync(0xffffffffu, s2, o);
            ss2 += __shfl_xor_sync(0xffffffffu, ss2, o);
        }
        if (lane == 0) {
            float mu  = s2 * (1.f / DIM);
            float var = ss2 * (1.f / DIM) - mu * mu;
            stats[0] = mu;
            stats[1] = rsqrtf(var + LN_EPS);
        }
    }
    __syncthreads();
    const float mu = stats[0], rstd = stats[1];

    const float4* gp = reinterpret_cast<const float4*>(gamma);
    const float4* bp = reinterpret_cast<const float4*>(beta);
    float4 g0 = gp[t], g1 = gp[t + 256];
    float4 b0 = bp[t], b1 = bp[t + 256];

    uint2* dst = reinterpret_cast<uint2*>(g_hn + (size_t)row * DIM);
    dst[t] = pack4((v0.x - mu) * rstd * g0.x + b0.x,
                   (v0.y - mu) * rstd * g0.y + b0.y,
                   (v0.z - mu) * rstd * g0.z + b0.z,
                   (v0.w - mu) * rstd * g0.w + b0.w);
    dst[t + 256] = pack4((v1.x - mu) * rstd * g1.x + b1.x,
                         (v1.y - mu) * rstd * g1.y + b1.y,
                         (v1.z - mu) * rstd * g1.z + b1.z,
                         (v1.w - mu) * rstd * g1.w + b1.w);
}

// ---------------------------------------------------------------------------
// Kernel: fp32 [R][C] -> bf16 transposed [C][R]
// ---------------------------------------------------------------------------
__global__ void transpose_bf16_kernel(const float* __restrict__ src, int R, int C,
                                      __nv_bfloat16* __restrict__ dst)
{
    __shared__ float tile[32][33];
    int x  = blockIdx.x * 32 + threadIdx.x;   // col in src
    int y0 = blockIdx.y * 32;                 // row base in src
#pragma unroll
    for (int j = 0; j < 32; j += 8)
        tile[threadIdx.y + j][threadIdx.x] = src[(size_t)(y0 + threadIdx.y + j) * C + x];
    __syncthreads();
    int xr  = blockIdx.y * 32 + threadIdx.x;  // fast index in dst (= src row)
    int yc0 = blockIdx.x * 32;                // dst row base (= src col)
#pragma unroll
    for (int j = 0; j < 32; j += 8)
        dst[(size_t)(yc0 + threadIdx.y + j) * R + xr] =
            __float2bfloat16_rn(tile[threadIdx.x][threadIdx.y + j]);
}

// ---------------------------------------------------------------------------
// Shared GEMM mainloop: C[128x128] tile, bf16 A [m][k], bf16 B [n][k],
// cp.async 2-stage pipeline, ldmatrix fragment loads.
// ---------------------------------------------------------------------------
__device__ __forceinline__ void load_tile_pair(
    unsigned sAbase, unsigned sBbase, int s,
    const __nv_bfloat16* __restrict__ Ag, int lda,
    const __nv_bfloat16* __restrict__ Bg, int ldb,
    int rowBase, int n0, int k0, int tid)
{
    const int r0i = tid >> 2;
    const int ci  = (tid & 3) * 8;
    unsigned dA = sAbase + (unsigned)(s * BM * BKP * 2);
    unsigned dB = sBbase + (unsigned)(s * BN * BKP * 2);
    const __nv_bfloat16* srcA = Ag + (size_t)rowBase * lda + k0 + ci;
    const __nv_bfloat16* srcB = Bg + (size_t)n0 * ldb + k0 + ci;
#pragma unroll
    for (int p = 0; p < 2; ++p) {
        int r = r0i + p * 64;
        cpa16(dA + (unsigned)((r * BKP + ci) * 2), srcA + (size_t)r * lda);
        cpa16(dB + (unsigned)((r * BKP + ci) * 2), srcB + (size_t)r * ldb);
    }
}

__device__ __forceinline__ void gemm_mainloop(
    const __nv_bfloat16* __restrict__ Ag, int lda,
    const __nv_bfloat16* __restrict__ Bg, int ldb,
    int Kdim, int rowBase, int n0,
    __nv_bfloat16* As, __nv_bfloat16* Bs,
    float c[4][4][4])
{
    const int tid  = threadIdx.x;
    const int warp = tid >> 5, lane = tid & 31;
    const int wm = warp >> 2, wn = warp & 3;

    const unsigned sAbase = smem_u32(As);
    const unsigned sBbase = smem_u32(Bs);

    // ldmatrix lane addressing (x4: reg j <- lanes 8j..8j+7 row addrs)
    const int aRow    = ((lane >> 3) & 1) * 8 + (lane & 7);  // a-regs: m0-7,k0-7 / m8-15,k0-7 / m0-7,k8-15 / m8-15,k8-15
    const int aColOff = (lane >> 4) * 8;
    const int bRow    = (lane >> 4) * 8 + (lane & 7);        // b-regs: n0-7,k0-7 / n0-7,k8-15 / n8-15,k0-7 / n8-15,k8-15
    const int bColOff = ((lane >> 3) & 1) * 8;

    const int niter = Kdim / BK;
    load_tile_pair(sAbase, sBbase, 0, Ag, lda, Bg, ldb, rowBase, n0, 0, tid);
    cpa_commit();

    for (int it = 0; it < niter; ++it) {
        cpa_wait<0>();
        __syncthreads();
        if (it + 1 < niter)
            load_tile_pair(sAbase, sBbase, (it + 1) & 1, Ag, lda, Bg, ldb,
                           rowBase, n0, (it + 1) * BK, tid);
        cpa_commit();

        const unsigned sA = sAbase + (unsigned)((it & 1) * BM * BKP * 2);
        const unsigned sB = sBbase + (unsigned)((it & 1) * BN * BKP * 2);
#pragma unroll
        for (int kk = 0; kk < BK; kk += 16) {
            unsigned a[4][4], b[4][2];
#pragma unroll
            for (int mi = 0; mi < 4; ++mi) {
                int mBase = wm * 64 + mi * 16;
                unsigned addr = sA + (unsigned)(((mBase + aRow) * BKP + kk + aColOff) * 2);
                ldsm_x4(a[mi][0], a[mi][1], a[mi][2], a[mi][3], addr);
            }
#pragma unroll
            for (int p = 0; p < 2; ++p) {
                int nBase = wn * 32 + p * 16;
                unsigned addr = sB + (unsigned)(((nBase + bRow) * BKP + kk + bColOff) * 2);
                ldsm_x4(b[2 * p][0], b[2 * p][1], b[2 * p + 1][0], b[2 * p + 1][1], addr);
            }
#pragma unroll
            for (int mi = 0; mi < 4; ++mi)
#pragma unroll
                for (int ni = 0; ni < 4; ++ni)
                    mma16816(c[mi][ni], a[mi], b[ni]);
        }
        __syncthreads();
    }
}

// ---------------------------------------------------------------------------
// GEMM1: z = SiLU( h_norm @ W_down + b_down )   (bf16 out to g_z)
// ---------------------------------------------------------------------------
__global__ __launch_bounds__(256, 2) void gemm1_kernel(const float* __restrict__ bd)
{
    __shared__ __align__(16) __nv_bfloat16 As[STAGES * BM * BKP];
    __shared__ __align__(16) __nv_bfloat16 Bs[STAGES * BN * BKP];

    const int tid  = threadIdx.x;
    const int warp = tid >> 5, lane = tid & 31;
    const int wm = warp >> 2, wn = warp & 3;
    const int group = lane >> 2, tg = lane & 3;
    const int rowBase = blockIdx.y * BM;
    const int n0      = blockIdx.x * BN;

    float c[4][4][4];
#pragma unroll
    for (int i = 0; i < 4; i++)
#pragma unroll
        for (int j = 0; j < 4; j++)
#pragma unroll
            for (int k = 0; k < 4; k++) c[i][j][k] = 0.f;

    gemm_mainloop(g_hn, DIM, g_WdT, DIM, DIM, rowBase, n0, As, Bs, c);

#pragma unroll
    for (int mi = 0; mi < 4; ++mi) {
        int r0 = rowBase + wm * 64 + mi * 16 + group;
#pragma unroll
        for (int ni = 0; ni < 4; ++ni) {
            int cc = n0 + wn * 32 + ni * 8 + tg * 2;
            float bd0 = bd[cc], bd1 = bd[cc + 1];
            *reinterpret_cast<__nv_bfloat162*>(&g_z[(size_t)r0 * DBOT + cc]) =
                __floats2bfloat162_rn(silu(c[mi][ni][0] + bd0), silu(c[mi][ni][1] + bd1));
            *reinterpret_cast<__nv_bfloat162*>(&g_z[(size_t)(r0 + 8) * DBOT + cc]) =
                __floats2bfloat162_rn(silu(c[mi][ni][2] + bd0), silu(c[mi][ni][3] + bd1));
        }
    }
}

// ---------------------------------------------------------------------------
// GEMM2: out = hidden + alpha * ( z @ W_up + b_up - hidden )
// ---------------------------------------------------------------------------
__global__ __launch_bounds__(256, 2) void gemm2_kernel(
    const float* __restrict__ hidden,
    const float* __restrict__ bu,
    const float* __restrict__ alpha_p,
    float* __restrict__ out)
{
    __shared__ __align__(16) __nv_bfloat16 As[STAGES * BM * BKP];
    __shared__ __align__(16) __nv_bfloat16 Bs[STAGES * BN * BKP];

    const int tid  = threadIdx.x;
    const int warp = tid >> 5, lane = tid & 31;
    const int wm = warp >> 2, wn = warp & 3;
    const int group = lane >> 2, tg = lane & 3;
    const int rowBase = blockIdx.y * BM;
    const int n0      = blockIdx.x * BN;

    float c[4][4][4];
#pragma unroll
    for (int i = 0; i < 4; i++)
#pragma unroll
        for (int j = 0; j < 4; j++)
#pragma unroll
            for (int k = 0; k < 4; k++) c[i][j][k] = 0.f;

    gemm_mainloop(g_z, DBOT, g_WuT, DBOT, DBOT, rowBase, n0, As, Bs, c);

    const float al = alpha_p[0];
#pragma unroll
    for (int mi = 0; mi < 4; ++mi) {
        int r0 = rowBase + wm * 64 + mi * 16 + group;
        int r1 = r0 + 8;
#pragma unroll
        for (int ni = 0; ni < 4; ++ni) {
            int cc = n0 + wn * 32 + ni * 8 + tg * 2;
            float bu0 = bu[cc], bu1 = bu[cc + 1];

            float2 h0 = *reinterpret_cast<const float2*>(hidden + (size_t)r0 * DIM + cc);
            float2 h1 = *reinterpret_cast<const float2*>(hidden + (size_t)r1 * DIM + cc);

            float2 o0, o1;
            o0.x = h0.x + al * (c[mi][ni][0] + bu0 - h0.x);
            o0.y = h0.y + al * (c[mi][ni][1] + bu1 - h0.y);
            o1.x = h1.x + al * (c[mi][ni][2] + bu0 - h1.x);
            o1.y = h1.y + al * (c[mi][ni][3] + bu1 - h1.y);

            *reinterpret_cast<float2*>(out + (size_t)r0 * DIM + cc) = o0;
            *reinterpret_cast<float2*>(out + (size_t)r1 * DIM + cc) = o1;
        }
    }
}

// ---------------------------------------------------------------------------
// Launch
// ---------------------------------------------------------------------------
extern "C" void kernel_launch(void* const* d_in, const int* in_sizes, int n_in,
                              void* d_out, int out_size) {
    const float* hidden = (const float*)d_in[0];
    const float* gamma  = (const float*)d_in[1];
    const float* beta   = (const float*)d_in[2];
    const float* Wd     = (const float*)d_in[3];
    const float* bd     = (const float*)d_in[4];
    const float* Wu     = (const float*)d_in[5];
    const float* bu     = (const float*)d_in[6];
    const float* alpha  = (const float*)d_in[7];
    float* out = (float*)d_out;

    __nv_bfloat16 *wdT, *wuT;
    cudaGetSymbolAddress((void**)&wdT, g_WdT);
    cudaGetSymbolAddress((void**)&wuT, g_WuT);

    dim3 tb(32, 8);
    transpose_bf16_kernel<<<dim3(DBOT / 32, DIM / 32), tb>>>(Wd, DIM, DBOT, wdT);
    transpose_bf16_kernel<<<dim3(DIM / 32, DBOT / 32), tb>>>(Wu, DBOT, DIM, wuT);
    ln_norm_kernel<<<T_ROWS, 256>>>(hidden, gamma, beta);
    gemm1_kernel<<<dim3(DBOT / BN, T_ROWS / BM), 256>>>(bd);
    gemm2_kernel<<<dim3(DIM / BN, T_ROWS / BM), 256>>>(hidden, bu, alpha, out);
}

// round 8
// speedup vs baseline: 2.8918x; 1.0287x over previous
#include <cuda_runtime.h>
#include <cuda_bf16.h>
#include <cstdint>

// Problem dims (fixed): B=4, S=4096, D=2048, Db=512
#define T_ROWS 16384
#define DIM    2048
#define DBOT   512
#define LN_EPS 1e-5f

// GEMM tiling
#define BM 128
#define BN 128
#define BK 32
#define BKP 40                        // 80B row stride: 16B-aligned cp.async, conflict-free ldmatrix
#define STAGES 4                      // cp.async pipeline depth (prefetch distance 3)
#define STAGE_ELTS ((BM + BN) * BKP)  // 10240 bf16 = 20480 B
#define DYN_BYTES (STAGES * STAGE_ELTS * 2)   // 81920 B

// ---------------------------------------------------------------------------
// Device scratch (allocation forbidden -> __device__ globals)
// ---------------------------------------------------------------------------
__device__ __nv_bfloat16 g_hn[(size_t)T_ROWS * DIM];   // 64 MB normalized hidden (bf16)
__device__ __nv_bfloat16 g_z[(size_t)T_ROWS * DBOT];   // 16 MB bottleneck activations
__device__ __nv_bfloat16 g_WdT[(size_t)DBOT * DIM];    // W_down^T bf16  [n][k]
__device__ __nv_bfloat16 g_WuT[(size_t)DIM * DBOT];    // W_up^T   bf16  [n][k]

// ---------------------------------------------------------------------------
// PTX helpers
// ---------------------------------------------------------------------------
__device__ __forceinline__ unsigned smem_u32(const void* p) {
    return (unsigned)__cvta_generic_to_shared(p);
}
__device__ __forceinline__ void cpa16(unsigned dst, const void* src) {
    asm volatile("cp.async.cg.shared.global [%0], [%1], 16;\n" :: "r"(dst), "l"(src));
}
__device__ __forceinline__ void cpa_commit() {
    asm volatile("cp.async.commit_group;\n");
}
template <int N>
__device__ __forceinline__ void cpa_wait() {
    asm volatile("cp.async.wait_group %0;\n" :: "n"(N));
}
__device__ __forceinline__ void ldsm_x4(unsigned& r0, unsigned& r1, unsigned& r2, unsigned& r3,
                                        unsigned addr) {
    asm volatile("ldmatrix.sync.aligned.m8n8.x4.shared.b16 {%0,%1,%2,%3}, [%4];\n"
                 : "=r"(r0), "=r"(r1), "=r"(r2), "=r"(r3) : "r"(addr));
}
__device__ __forceinline__ void mma16816(float c[4], const unsigned a[4], const unsigned b[2]) {
    asm volatile(
        "mma.sync.aligned.m16n8k16.row.col.f32.bf16.bf16.f32 "
        "{%0,%1,%2,%3}, {%4,%5,%6,%7}, {%8,%9}, {%0,%1,%2,%3};\n"
        : "+f"(c[0]), "+f"(c[1]), "+f"(c[2]), "+f"(c[3])
        : "r"(a[0]), "r"(a[1]), "r"(a[2]), "r"(a[3]), "r"(b[0]), "r"(b[1]));
}
__device__ __forceinline__ float silu(float v) {
    return v * (1.f / (1.f + __expf(-v)));
}
__device__ __forceinline__ uint2 pack4(float a, float b, float c, float d) {
    __nv_bfloat162 p0 = __floats2bfloat162_rn(a, b);
    __nv_bfloat162 p1 = __floats2bfloat162_rn(c, d);
    uint2 u;
    u.x = *reinterpret_cast<unsigned*>(&p0);
    u.y = *reinterpret_cast<unsigned*>(&p1);
    return u;
}

// ---------------------------------------------------------------------------
// Fused LayerNorm -> bf16 h_norm (one block per row, read+write once)
// ---------------------------------------------------------------------------
__global__ __launch_bounds__(256) void ln_norm_kernel(
    const float* __restrict__ hidden,
    const float* __restrict__ gamma,
    const float* __restrict__ beta)
{
    const int row = blockIdx.x;
    const int t = threadIdx.x;
    const int warp = t >> 5, lane = t & 31;

    const float4* hp = reinterpret_cast<const float4*>(hidden + (size_t)row * DIM);
    float4 v0 = hp[t], v1 = hp[t + 256];

    float s  = v0.x + v0.y + v0.z + v0.w + v1.x + v1.y + v1.z + v1.w;
    float ss = v0.x * v0.x + v0.y * v0.y + v0.z * v0.z + v0.w * v0.w
             + v1.x * v1.x + v1.y * v1.y + v1.z * v1.z + v1.w * v1.w;
#pragma unroll
    for (int o = 16; o > 0; o >>= 1) {
        s  += __shfl_xor_sync(0xffffffffu, s, o);
        ss += __shfl_xor_sync(0xffffffffu, ss, o);
    }
    __shared__ float rs[8], rss[8], stats[2];
    if (lane == 0) { rs[warp] = s; rss[warp] = ss; }
    __syncthreads();
    if (warp == 0) {
        float s2  = (lane < 8) ? rs[lane]  : 0.f;
        float ss2 = (lane < 8) ? rss[lane] : 0.f;
#pragma unroll
        for (int o = 4; o > 0; o >>= 1) {
            s2  += __shfl_xor_sync(0xffffffffu, s2, o);
            ss2 += __shfl_xor_sync(0xffffffffu, ss2, o);
        }
        if (lane == 0) {
            float mu  = s2 * (1.f / DIM);
            float var = ss2 * (1.f / DIM) - mu * mu;
            stats[0] = mu;
            stats[1] = rsqrtf(var + LN_EPS);
        }
    }
    __syncthreads();
    const float mu = stats[0], rstd = stats[1];

    const float4* gp = reinterpret_cast<const float4*>(gamma);
    const float4* bp = reinterpret_cast<const float4*>(beta);
    float4 g0 = gp[t], g1 = gp[t + 256];
    float4 b0 = bp[t], b1 = bp[t + 256];

    uint2* dst = reinterpret_cast<uint2*>(g_hn + (size_t)row * DIM);
    dst[t] = pack4((v0.x - mu) * rstd * g0.x + b0.x,
                   (v0.y - mu) * rstd * g0.y + b0.y,
                   (v0.z - mu) * rstd * g0.z + b0.z,
                   (v0.w - mu) * rstd * g0.w + b0.w);
    dst[t + 256] = pack4((v1.x - mu) * rstd * g1.x + b1.x,
                         (v1.y - mu) * rstd * g1.y + b1.y,
                         (v1.z - mu) * rstd * g1.z + b1.z,
                         (v1.w - mu) * rstd * g1.w + b1.w);
}

// ---------------------------------------------------------------------------
// fp32 [R][C] -> bf16 transposed [C][R]
// ---------------------------------------------------------------------------
__global__ void transpose_bf16_kernel(const float* __restrict__ src, int R, int C,
                                      __nv_bfloat16* __restrict__ dst)
{
    __shared__ float tile[32][33];
    int x  = blockIdx.x * 32 + threadIdx.x;
    int y0 = blockIdx.y * 32;
#pragma unroll
    for (int j = 0; j < 32; j += 8)
        tile[threadIdx.y + j][threadIdx.x] = src[(size_t)(y0 + threadIdx.y + j) * C + x];
    __syncthreads();
    int xr  = blockIdx.y * 32 + threadIdx.x;
    int yc0 = blockIdx.x * 32;
#pragma unroll
    for (int j = 0; j < 32; j += 8)
        dst[(size_t)(yc0 + threadIdx.y + j) * R + xr] =
            __float2bfloat16_rn(tile[threadIdx.x][threadIdx.y + j]);
}

// ---------------------------------------------------------------------------
// Tile loader: A[128 x 32] + B[128 x 32] bf16, 16B cp.async per op.
// dst offsets: (r*40 + ci)*2 = 80r + 16ci -> always 16B aligned.
// ---------------------------------------------------------------------------
__device__ __forceinline__ void load_tile_pair(
    unsigned sbase, int slot,
    const __nv_bfloat16* __restrict__ Ag, int lda,
    const __nv_bfloat16* __restrict__ Bg, int ldb,
    int rowBase, int n0, int k0, int tid)
{
    const int r0i = tid >> 2;
    const int ci  = (tid & 3) * 8;
    unsigned dA = sbase + (unsigned)(slot * STAGE_ELTS * 2);
    unsigned dB = dA + (unsigned)(BM * BKP * 2);
    const __nv_bfloat16* srcA = Ag + (size_t)rowBase * lda + k0 + ci;
    const __nv_bfloat16* srcB = Bg + (size_t)n0 * ldb + k0 + ci;
#pragma unroll
    for (int p = 0; p < 2; ++p) {
        int r = r0i + p * 64;
        cpa16(dA + (unsigned)((r * BKP + ci) * 2), srcA + (size_t)r * lda);
        cpa16(dB + (unsigned)((r * BKP + ci) * 2), srcB + (size_t)r * ldb);
    }
}

// ---------------------------------------------------------------------------
// Shared GEMM mainloop: 4-stage cp.async pipeline (prefetch distance 3),
// one __syncthreads per K-tile.
// Safety: at iter 'it' we compute slot it%4 and refill slot (it+3)%4, which
// was last computed at iter it-1 -> the top-of-loop sync orders RAW/WAR.
// ---------------------------------------------------------------------------
__device__ __forceinline__ void gemm_mainloop(
    const __nv_bfloat16* __restrict__ Ag, int lda,
    const __nv_bfloat16* __restrict__ Bg, int ldb,
    int Kdim, int rowBase, int n0,
    unsigned sbase,
    float c[4][4][4])
{
    const int tid  = threadIdx.x;
    const int warp = tid >> 5, lane = tid & 31;
    const int wm = warp >> 2, wn = warp & 3;

    // ldmatrix lane addressing (x4: reg j <- lanes 8j..8j+7 row addrs)
    const int aRow    = ((lane >> 3) & 1) * 8 + (lane & 7);
    const int aColOff = (lane >> 4) * 8;
    const int bRow    = (lane >> 4) * 8 + (lane & 7);
    const int bColOff = ((lane >> 3) & 1) * 8;

    const int niter = Kdim / BK;

    // prologue: prefetch tiles 0..2 (one commit group each)
    load_tile_pair(sbase, 0, Ag, lda, Bg, ldb, rowBase, n0, 0, tid);
    cpa_commit();
    load_tile_pair(sbase, 1, Ag, lda, Bg, ldb, rowBase, n0, BK, tid);
    cpa_commit();
    load_tile_pair(sbase, 2, Ag, lda, Bg, ldb, rowBase, n0, 2 * BK, tid);
    cpa_commit();

    int slot = 0, nslot = 3;
    for (int it = 0; it < niter; ++it) {
        cpa_wait<2>();          // tile 'it' resident (tiles it+1, it+2 may be in flight)
        __syncthreads();

        if (it + 3 < niter)
            load_tile_pair(sbase, nslot, Ag, lda, Bg, ldb, rowBase, n0, (it + 3) * BK, tid);
        cpa_commit();           // commit every iter (possibly empty) for uniform accounting

        const unsigned sA = sbase + (unsigned)(slot * STAGE_ELTS * 2);
        const unsigned sB = sA + (unsigned)(BM * BKP * 2);
#pragma unroll
        for (int kk = 0; kk < BK; kk += 16) {
            unsigned a[4][4], b[4][2];
#pragma unroll
            for (int mi = 0; mi < 4; ++mi) {
                int mBase = wm * 64 + mi * 16;
                unsigned addr = sA + (unsigned)(((mBase + aRow) * BKP + kk + aColOff) * 2);
                ldsm_x4(a[mi][0], a[mi][1], a[mi][2], a[mi][3], addr);
            }
#pragma unroll
            for (int p = 0; p < 2; ++p) {
                int nBase = wn * 32 + p * 16;
                unsigned addr = sB + (unsigned)(((nBase + bRow) * BKP + kk + bColOff) * 2);
                ldsm_x4(b[2 * p][0], b[2 * p][1], b[2 * p + 1][0], b[2 * p + 1][1], addr);
            }
#pragma unroll
            for (int mi = 0; mi < 4; ++mi)
#pragma unroll
                for (int ni = 0; ni < 4; ++ni)
                    mma16816(c[mi][ni], a[mi], b[ni]);
        }

        slot  = (slot == STAGES - 1) ? 0 : slot + 1;
        nslot = (nslot == STAGES - 1) ? 0 : nslot + 1;
    }
}

// ---------------------------------------------------------------------------
// GEMM1: z = SiLU( h_norm @ W_down + b_down )   (bf16 out to g_z)
// ---------------------------------------------------------------------------
__global__ __launch_bounds__(256, 2) void gemm1_kernel(const float* __restrict__ bd)
{
    extern __shared__ __align__(16) __nv_bfloat16 smem[];

    const int tid  = threadIdx.x;
    const int warp = tid >> 5, lane = tid & 31;
    const int wm = warp >> 2, wn = warp & 3;
    const int group = lane >> 2, tg = lane & 3;
    const int rowBase = blockIdx.y * BM;
    const int n0      = blockIdx.x * BN;

    float c[4][4][4];
#pragma unroll
    for (int i = 0; i < 4; i++)
#pragma unroll
        for (int j = 0; j < 4; j++)
#pragma unroll
            for (int k = 0; k < 4; k++) c[i][j][k] = 0.f;

    gemm_mainloop(g_hn, DIM, g_WdT, DIM, DIM, rowBase, n0, smem_u32(smem), c);

#pragma unroll
    for (int mi = 0; mi < 4; ++mi) {
        int r0 = rowBase + wm * 64 + mi * 16 + group;
#pragma unroll
        for (int ni = 0; ni < 4; ++ni) {
            int cc = n0 + wn * 32 + ni * 8 + tg * 2;
            float bd0 = bd[cc], bd1 = bd[cc + 1];
            *reinterpret_cast<__nv_bfloat162*>(&g_z[(size_t)r0 * DBOT + cc]) =
                __floats2bfloat162_rn(silu(c[mi][ni][0] + bd0), silu(c[mi][ni][1] + bd1));
            *reinterpret_cast<__nv_bfloat162*>(&g_z[(size_t)(r0 + 8) * DBOT + cc]) =
                __floats2bfloat162_rn(silu(c[mi][ni][2] + bd0), silu(c[mi][ni][3] + bd1));
        }
    }
}

// ---------------------------------------------------------------------------
// GEMM2: out = hidden + alpha * ( z @ W_up + b_up - hidden )
// ---------------------------------------------------------------------------
__global__ __launch_bounds__(256, 2) void gemm2_kernel(
    const float* __restrict__ hidden,
    const float* __restrict__ bu,
    const float* __restrict__ alpha_p,
    float* __restrict__ out)
{
    extern __shared__ __align__(16) __nv_bfloat16 smem[];

    const int tid  = threadIdx.x;
    const int warp = tid >> 5, lane = tid & 31;
    const int wm = warp >> 2, wn = warp & 3;
    const int group = lane >> 2, tg = lane & 3;
    const int rowBase = blockIdx.y * BM;
    const int n0      = blockIdx.x * BN;

    float c[4][4][4];
#pragma unroll
    for (int i = 0; i < 4; i++)
#pragma unroll
        for (int j = 0; j < 4; j++)
#pragma unroll
            for (int k = 0; k < 4; k++) c[i][j][k] = 0.f;

    gemm_mainloop(g_z, DBOT, g_WuT, DBOT, DBOT, rowBase, n0, smem_u32(smem), c);

    const float al = alpha_p[0];
#pragma unroll
    for (int mi = 0; mi < 4; ++mi) {
        int r0 = rowBase + wm * 64 + mi * 16 + group;
        int r1 = r0 + 8;
#pragma unroll
        for (int ni = 0; ni < 4; ++ni) {
            int cc = n0 + wn * 32 + ni * 8 + tg * 2;
            float bu0 = bu[cc], bu1 = bu[cc + 1];

            float2 h0 = *reinterpret_cast<const float2*>(hidden + (size_t)r0 * DIM + cc);
            float2 h1 = *reinterpret_cast<const float2*>(hidden + (size_t)r1 * DIM + cc);

            float2 o0, o1;
            o0.x = h0.x + al * (c[mi][ni][0] + bu0 - h0.x);
            o0.y = h0.y + al * (c[mi][ni][1] + bu1 - h0.y);
            o1.x = h1.x + al * (c[mi][ni][2] + bu0 - h1.x);
            o1.y = h1.y + al * (c[mi][ni][3] + bu1 - h1.y);

            *reinterpret_cast<float2*>(out + (size_t)r0 * DIM + cc) = o0;
            *reinterpret_cast<float2*>(out + (size_t)r1 * DIM + cc) = o1;
        }
    }
}

// ---------------------------------------------------------------------------
// Launch
// ---------------------------------------------------------------------------
extern "C" void kernel_launch(void* const* d_in, const int* in_sizes, int n_in,
                              void* d_out, int out_size) {
    const float* hidden = (const float*)d_in[0];
    const float* gamma  = (const float*)d_in[1];
    const float* beta   = (const float*)d_in[2];
    const float* Wd     = (const float*)d_in[3];
    const float* bd     = (const float*)d_in[4];
    const float* Wu     = (const float*)d_in[5];
    const float* bu     = (const float*)d_in[6];
    const float* alpha  = (const float*)d_in[7];
    float* out = (float*)d_out;

    __nv_bfloat16 *wdT, *wuT;
    cudaGetSymbolAddress((void**)&wdT, g_WdT);
    cudaGetSymbolAddress((void**)&wuT, g_WuT);

    cudaFuncSetAttribute(gemm1_kernel, cudaFuncAttributeMaxDynamicSharedMemorySize, DYN_BYTES);
    cudaFuncSetAttribute(gemm2_kernel, cudaFuncAttributeMaxDynamicSharedMemorySize, DYN_BYTES);

    dim3 tb(32, 8);
    transpose_bf16_kernel<<<dim3(DBOT / 32, DIM / 32), tb>>>(Wd, DIM, DBOT, wdT);
    transpose_bf16_kernel<<<dim3(DIM / 32, DBOT / 32), tb>>>(Wu, DBOT, DIM, wuT);
    ln_norm_kernel<<<T_ROWS, 256>>>(hidden, gamma, beta);
    gemm1_kernel<<<dim3(DBOT / BN, T_ROWS / BM), 256, DYN_BYTES>>>(bd);
    gemm2_kernel<<<dim3(DIM / BN, T_ROWS / BM), 256, DYN_BYTES>>>(hidden, bu, alpha, out);
}

// round 9
// speedup vs baseline: 3.1371x; 1.0848x over previous
#include <cuda_runtime.h>
#include <cuda_bf16.h>
#include <cstdint>

// Problem dims (fixed): B=4, S=4096, D=2048, Db=512
#define T_ROWS 16384
#define DIM    2048
#define DBOT   512
#define LN_EPS 1e-5f

// FP8 GEMM tiling (byte units; fp8 = 1 B/elt)
#define BM 128
#define BN 128
#define KTB 64                         // K bytes per tile (64 fp8 elements)
#define BKB 80                         // padded row stride bytes (16B-aligned cp.async, conflict-free)
#define STAGES 4
#define STAGE_BYTES ((BM + BN) * BKB)  // 20480
#define DYN_BYTES (STAGES * STAGE_BYTES)  // 81920

#define WD_SCALE 64.f
#define WU_SCALE 32.f

// ---------------------------------------------------------------------------
// Device scratch (allocation forbidden -> __device__ globals)
// ---------------------------------------------------------------------------
__device__ unsigned char g_hn[(size_t)T_ROWS * DIM];    // 32 MB fp8 normalized hidden
__device__ unsigned char g_z[(size_t)T_ROWS * DBOT];    // 8 MB fp8 bottleneck activations
__device__ unsigned char g_WdT[(size_t)DBOT * DIM];     // W_down^T * 64, fp8  [n][k]
__device__ unsigned char g_WuT[(size_t)DIM * DBOT];     // W_up^T   * 32, fp8  [n][k]

// ---------------------------------------------------------------------------
// PTX helpers
// ---------------------------------------------------------------------------
__device__ __forceinline__ unsigned smem_u32(const void* p) {
    return (unsigned)__cvta_generic_to_shared(p);
}
__device__ __forceinline__ void cpa16(unsigned dst, const void* src) {
    asm volatile("cp.async.cg.shared.global [%0], [%1], 16;\n" :: "r"(dst), "l"(src));
}
__device__ __forceinline__ void cpa_commit() {
    asm volatile("cp.async.commit_group;\n");
}
template <int N>
__device__ __forceinline__ void cpa_wait() {
    asm volatile("cp.async.wait_group %0;\n" :: "n"(N));
}
__device__ __forceinline__ void ldsm_x4(unsigned& r0, unsigned& r1, unsigned& r2, unsigned& r3,
                                        unsigned addr) {
    asm volatile("ldmatrix.sync.aligned.m8n8.x4.shared.b16 {%0,%1,%2,%3}, [%4];\n"
                 : "=r"(r0), "=r"(r1), "=r"(r2), "=r"(r3) : "r"(addr));
}
// FP8 e4m3 MMA: 16x8x32, fp32 accumulate (2x FLOP per instruction vs bf16 16816)
__device__ __forceinline__ void mma_f8(float c[4], const unsigned a[4], const unsigned b[2]) {
    asm volatile(
        "mma.sync.aligned.m16n8k32.row.col.f32.e4m3.e4m3.f32 "
        "{%0,%1,%2,%3}, {%4,%5,%6,%7}, {%8,%9}, {%0,%1,%2,%3};\n"
        : "+f"(c[0]), "+f"(c[1]), "+f"(c[2]), "+f"(c[3])
        : "r"(a[0]), "r"(a[1]), "r"(a[2]), "r"(a[3]), "r"(b[0]), "r"(b[1]));
}
// fp8 packing: cvt.rn.satfinite.e4m3x2.f32 d, a, b -> d[15:8]=cvt(a), d[7:0]=cvt(b)
__device__ __forceinline__ unsigned short pack_fp8x2(float lo, float hi) {
    unsigned short r;
    asm("cvt.rn.satfinite.e4m3x2.f32 %0, %1, %2;" : "=h"(r) : "f"(hi), "f"(lo));
    return r;
}
__device__ __forceinline__ unsigned pack_fp8x4(float a, float b, float c, float d) {
    unsigned short lo = pack_fp8x2(a, b);
    unsigned short hi = pack_fp8x2(c, d);
    return (unsigned)lo | ((unsigned)hi << 16);
}
__device__ __forceinline__ unsigned char f2fp8(float v) {
    return (unsigned char)pack_fp8x2(v, 0.f);
}
__device__ __forceinline__ float silu(float v) {
    return v * (1.f / (1.f + __expf(-v)));
}

// ---------------------------------------------------------------------------
// Fused LayerNorm -> fp8 h_norm (one block per row, read+write once)
// ---------------------------------------------------------------------------
__global__ __launch_bounds__(256) void ln_norm_kernel(
    const float* __restrict__ hidden,
    const float* __restrict__ gamma,
    const float* __restrict__ beta)
{
    const int row = blockIdx.x;
    const int t = threadIdx.x;
    const int warp = t >> 5, lane = t & 31;

    const float4* hp = reinterpret_cast<const float4*>(hidden + (size_t)row * DIM);
    float4 v0 = hp[t], v1 = hp[t + 256];

    float s  = v0.x + v0.y + v0.z + v0.w + v1.x + v1.y + v1.z + v1.w;
    float ss = v0.x * v0.x + v0.y * v0.y + v0.z * v0.z + v0.w * v0.w
             + v1.x * v1.x + v1.y * v1.y + v1.z * v1.z + v1.w * v1.w;
#pragma unroll
    for (int o = 16; o > 0; o >>= 1) {
        s  += __shfl_xor_sync(0xffffffffu, s, o);
        ss += __shfl_xor_sync(0xffffffffu, ss, o);
    }
    __shared__ float rs[8], rss[8], stats[2];
    if (lane == 0) { rs[warp] = s; rss[warp] = ss; }
    __syncthreads();
    if (warp == 0) {
        float s2  = (lane < 8) ? rs[lane]  : 0.f;
        float ss2 = (lane < 8) ? rss[lane] : 0.f;
#pragma unroll
        for (int o = 4; o > 0; o >>= 1) {
            s2  += __shfl_xor_sync(0xffffffffu, s2, o);
            ss2 += __shfl_xor_sync(0xffffffffu, ss2, o);
        }
        if (lane == 0) {
            float mu  = s2 * (1.f / DIM);
            float var = ss2 * (1.f / DIM) - mu * mu;
            stats[0] = mu;
            stats[1] = rsqrtf(var + LN_EPS);
        }
    }
    __syncthreads();
    const float mu = stats[0], rstd = stats[1];

    const float4* gp = reinterpret_cast<const float4*>(gamma);
    const float4* bp = reinterpret_cast<const float4*>(beta);
    float4 g0 = gp[t], g1 = gp[t + 256];
    float4 b0 = bp[t], b1 = bp[t + 256];

    unsigned* dst = reinterpret_cast<unsigned*>(g_hn + (size_t)row * DIM);
    dst[t] = pack_fp8x4((v0.x - mu) * rstd * g0.x + b0.x,
                        (v0.y - mu) * rstd * g0.y + b0.y,
                        (v0.z - mu) * rstd * g0.z + b0.z,
                        (v0.w - mu) * rstd * g0.w + b0.w);
    dst[t + 256] = pack_fp8x4((v1.x - mu) * rstd * g1.x + b1.x,
                              (v1.y - mu) * rstd * g1.y + b1.y,
                              (v1.z - mu) * rstd * g1.z + b1.z,
                              (v1.w - mu) * rstd * g1.w + b1.w);
}

// ---------------------------------------------------------------------------
// fp32 [R][C] -> fp8 transposed [C][R], scaled
// ---------------------------------------------------------------------------
__global__ void transpose_fp8_kernel(const float* __restrict__ src, int R, int C,
                                     unsigned char* __restrict__ dst, float scale)
{
    __shared__ float tile[32][33];
    int x  = blockIdx.x * 32 + threadIdx.x;
    int y0 = blockIdx.y * 32;
#pragma unroll
    for (int j = 0; j < 32; j += 8)
        tile[threadIdx.y + j][threadIdx.x] = src[(size_t)(y0 + threadIdx.y + j) * C + x];
    __syncthreads();
    int xr  = blockIdx.y * 32 + threadIdx.x;
    int yc0 = blockIdx.x * 32;
#pragma unroll
    for (int j = 0; j < 32; j += 8)
        dst[(size_t)(yc0 + threadIdx.y + j) * R + xr] =
            f2fp8(tile[threadIdx.x][threadIdx.y + j] * scale);
}

// ---------------------------------------------------------------------------
// Tile loader: A[128 x 64B] + B[128 x 64B] fp8, 16B cp.async per op.
// dst offsets: r*80 + ci*16 -> always 16B aligned.
// ---------------------------------------------------------------------------
__device__ __forceinline__ void load_tile_pair(
    unsigned sbase, int slot,
    const unsigned char* __restrict__ Ag, int ldaB,
    const unsigned char* __restrict__ Bg, int ldbB,
    int rowBase, int n0, int k0B, int tid)
{
    const int r0i = tid >> 2;
    const int ci  = (tid & 3) * 16;
    unsigned dA = sbase + (unsigned)(slot * STAGE_BYTES);
    unsigned dB = dA + (unsigned)(BM * BKB);
    const unsigned char* srcA = Ag + (size_t)rowBase * ldaB + k0B + ci;
    const unsigned char* srcB = Bg + (size_t)n0 * ldbB + k0B + ci;
#pragma unroll
    for (int p = 0; p < 2; ++p) {
        int r = r0i + p * 64;
        cpa16(dA + (unsigned)(r * BKB + ci), srcA + (size_t)r * ldaB);
        cpa16(dB + (unsigned)(r * BKB + ci), srcB + (size_t)r * ldbB);
    }
}

// ---------------------------------------------------------------------------
// Shared FP8 GEMM mainloop: 4-stage cp.async pipeline, one sync per K-tile.
// fp8 m16n8k32 fragments == bf16 m16n8k16 fragments at the byte level, so
// the (verified) ldmatrix addressing carries over unchanged.
// ---------------------------------------------------------------------------
__device__ __forceinline__ void gemm_mainloop(
    const unsigned char* __restrict__ Ag, int ldaB,
    const unsigned char* __restrict__ Bg, int ldbB,
    int KBytes, int rowBase, int n0,
    unsigned sbase,
    float c[4][4][4])
{
    const int tid  = threadIdx.x;
    const int warp = tid >> 5, lane = tid & 31;
    const int wm = warp >> 2, wn = warp & 3;

    const int aRow     = ((lane >> 3) & 1) * 8 + (lane & 7);
    const int aColOffB = (lane >> 4) * 16;
    const int bRow     = (lane >> 4) * 8 + (lane & 7);
    const int bColOffB = ((lane >> 3) & 1) * 16;

    const int niter = KBytes / KTB;

    load_tile_pair(sbase, 0, Ag, ldaB, Bg, ldbB, rowBase, n0, 0, tid);
    cpa_commit();
    load_tile_pair(sbase, 1, Ag, ldaB, Bg, ldbB, rowBase, n0, KTB, tid);
    cpa_commit();
    load_tile_pair(sbase, 2, Ag, ldaB, Bg, ldbB, rowBase, n0, 2 * KTB, tid);
    cpa_commit();

    int slot = 0, nslot = 3;
    for (int it = 0; it < niter; ++it) {
        cpa_wait<2>();
        __syncthreads();

        if (it + 3 < niter)
            load_tile_pair(sbase, nslot, Ag, ldaB, Bg, ldbB, rowBase, n0, (it + 3) * KTB, tid);
        cpa_commit();

        const unsigned sA = sbase + (unsigned)(slot * STAGE_BYTES);
        const unsigned sB = sA + (unsigned)(BM * BKB);
#pragma unroll
        for (int kkB = 0; kkB < KTB; kkB += 32) {    // one m16n8k32 step = 32 B of K
            unsigned a[4][4], b[4][2];
#pragma unroll
            for (int mi = 0; mi < 4; ++mi) {
                int mBase = wm * 64 + mi * 16;
                unsigned addr = sA + (unsigned)((mBase + aRow) * BKB + kkB + aColOffB);
                ldsm_x4(a[mi][0], a[mi][1], a[mi][2], a[mi][3], addr);
            }
#pragma unroll
            for (int p = 0; p < 2; ++p) {
                int nBase = wn * 32 + p * 16;
                unsigned addr = sB + (unsigned)((nBase + bRow) * BKB + kkB + bColOffB);
                ldsm_x4(b[2 * p][0], b[2 * p][1], b[2 * p + 1][0], b[2 * p + 1][1], addr);
            }
#pragma unroll
            for (int mi = 0; mi < 4; ++mi)
#pragma unroll
                for (int ni = 0; ni < 4; ++ni)
                    mma_f8(c[mi][ni], a[mi], b[ni]);
        }

        slot  = (slot == STAGES - 1) ? 0 : slot + 1;
        nslot = (nslot == STAGES - 1) ? 0 : nslot + 1;
    }
}

// ---------------------------------------------------------------------------
// GEMM1: z = SiLU( h_norm @ (W_down*64) / 64 + b_down )  -> fp8 g_z
// ---------------------------------------------------------------------------
__global__ __launch_bounds__(256, 2) void gemm1_kernel(const float* __restrict__ bd)
{
    extern __shared__ __align__(16) unsigned char smem[];

    const int tid  = threadIdx.x;
    const int warp = tid >> 5, lane = tid & 31;
    const int wm = warp >> 2, wn = warp & 3;
    const int group = lane >> 2, tg = lane & 3;
    const int rowBase = blockIdx.y * BM;
    const int n0      = blockIdx.x * BN;

    float c[4][4][4];
#pragma unroll
    for (int i = 0; i < 4; i++)
#pragma unroll
        for (int j = 0; j < 4; j++)
#pragma unroll
            for (int k = 0; k < 4; k++) c[i][j][k] = 0.f;

    gemm_mainloop(g_hn, DIM, g_WdT, DIM, DIM, rowBase, n0, smem_u32(smem), c);

    const float inv = 1.f / WD_SCALE;
#pragma unroll
    for (int mi = 0; mi < 4; ++mi) {
        int r0 = rowBase + wm * 64 + mi * 16 + group;
#pragma unroll
        for (int ni = 0; ni < 4; ++ni) {
            int cc = n0 + wn * 32 + ni * 8 + tg * 2;
            float bd0 = bd[cc], bd1 = bd[cc + 1];
            *reinterpret_cast<unsigned short*>(&g_z[(size_t)r0 * DBOT + cc]) =
                pack_fp8x2(silu(c[mi][ni][0] * inv + bd0), silu(c[mi][ni][1] * inv + bd1));
            *reinterpret_cast<unsigned short*>(&g_z[(size_t)(r0 + 8) * DBOT + cc]) =
                pack_fp8x2(silu(c[mi][ni][2] * inv + bd0), silu(c[mi][ni][3] * inv + bd1));
        }
    }
}

// ---------------------------------------------------------------------------
// GEMM2: out = hidden + alpha * ( z @ (W_up*32)/32 + b_up - hidden )
// ---------------------------------------------------------------------------
__global__ __launch_bounds__(256, 2) void gemm2_kernel(
    const float* __restrict__ hidden,
    const float* __restrict__ bu,
    const float* __restrict__ alpha_p,
    float* __restrict__ out)
{
    extern __shared__ __align__(16) unsigned char smem[];

    const int tid  = threadIdx.x;
    const int warp = tid >> 5, lane = tid & 31;
    const int wm = warp >> 2, wn = warp & 3;
    const int group = lane >> 2, tg = lane & 3;
    const int rowBase = blockIdx.y * BM;
    const int n0      = blockIdx.x * BN;

    float c[4][4][4];
#pragma unroll
    for (int i = 0; i < 4; i++)
#pragma unroll
        for (int j = 0; j < 4; j++)
#pragma unroll
            for (int k = 0; k < 4; k++) c[i][j][k] = 0.f;

    gemm_mainloop(g_z, DBOT, g_WuT, DBOT, DBOT, rowBase, n0, smem_u32(smem), c);

    const float al = alpha_p[0];
    const float inv = 1.f / WU_SCALE;
#pragma unroll
    for (int mi = 0; mi < 4; ++mi) {
        int r0 = rowBase + wm * 64 + mi * 16 + group;
        int r1 = r0 + 8;
#pragma unroll
        for (int ni = 0; ni < 4; ++ni) {
            int cc = n0 + wn * 32 + ni * 8 + tg * 2;
            float bu0 = bu[cc], bu1 = bu[cc + 1];

            float2 h0 = *reinterpret_cast<const float2*>(hidden + (size_t)r0 * DIM + cc);
            float2 h1 = *reinterpret_cast<const float2*>(hidden + (size_t)r1 * DIM + cc);

            float2 o0, o1;
            o0.x = h0.x + al * (c[mi][ni][0] * inv + bu0 - h0.x);
            o0.y = h0.y + al * (c[mi][ni][1] * inv + bu1 - h0.y);
            o1.x = h1.x + al * (c[mi][ni][2] * inv + bu0 - h1.x);
            o1.y = h1.y + al * (c[mi][ni][3] * inv + bu1 - h1.y);

            *reinterpret_cast<float2*>(out + (size_t)r0 * DIM + cc) = o0;
            *reinterpret_cast<float2*>(out + (size_t)r1 * DIM + cc) = o1;
        }
    }
}

// ---------------------------------------------------------------------------
// Launch
// ---------------------------------------------------------------------------
extern "C" void kernel_launch(void* const* d_in, const int* in_sizes, int n_in,
                              void* d_out, int out_size) {
    const float* hidden = (const float*)d_in[0];
    const float* gamma  = (const float*)d_in[1];
    const float* beta   = (const float*)d_in[2];
    const float* Wd     = (const float*)d_in[3];
    const float* bd     = (const float*)d_in[4];
    const float* Wu     = (const float*)d_in[5];
    const float* bu     = (const float*)d_in[6];
    const float* alpha  = (const float*)d_in[7];
    float* out = (float*)d_out;

    unsigned char *wdT, *wuT;
    cudaGetSymbolAddress((void**)&wdT, g_WdT);
    cudaGetSymbolAddress((void**)&wuT, g_WuT);

    cudaFuncSetAttribute(gemm1_kernel, cudaFuncAttributeMaxDynamicSharedMemorySize, DYN_BYTES);
    cudaFuncSetAttribute(gemm2_kernel, cudaFuncAttributeMaxDynamicSharedMemorySize, DYN_BYTES);

    dim3 tb(32, 8);
    transpose_fp8_kernel<<<dim3(DBOT / 32, DIM / 32), tb>>>(Wd, DIM, DBOT, wdT, WD_SCALE);
    transpose_fp8_kernel<<<dim3(DIM / 32, DBOT / 32), tb>>>(Wu, DBOT, DIM, wuT, WU_SCALE);
    ln_norm_kernel<<<T_ROWS, 256>>>(hidden, gamma, beta);
    gemm1_kernel<<<dim3(DBOT / BN, T_ROWS / BM), 256, DYN_BYTES>>>(bd);
    gemm2_kernel<<<dim3(DIM / BN, T_ROWS / BM), 256, DYN_BYTES>>>(hidden, bu, alpha, out);
}

// round 10
// speedup vs baseline: 3.1880x; 1.0162x over previous
#include <cuda_runtime.h>
#include <cuda_bf16.h>
#include <cstdint>

// Problem dims (fixed): B=4, S=4096, D=2048, Db=512
#define T_ROWS 16384
#define DIM    2048
#define DBOT   512
#define LN_EPS 1e-5f

// FP8 GEMM tiling (byte units; fp8 = 1 B/elt)
#define BM 128
#define BN 128
#define KTB 64                         // K bytes per tile (64 fp8 elements)
#define BKB 80                         // padded row stride bytes (16B-aligned cp.async, conflict-free)
#define STAGES 4
#define STAGE_BYTES ((BM + BN) * BKB)  // 20480
#define DYN_BYTES (STAGES * STAGE_BYTES)  // 81920

#define WD_SCALE 64.f
#define WU_SCALE 32.f

// ---------------------------------------------------------------------------
// Device scratch (allocation forbidden -> __device__ globals)
// ---------------------------------------------------------------------------
__device__ unsigned char g_hn[(size_t)T_ROWS * DIM];    // 32 MB fp8 normalized hidden
__device__ unsigned char g_z[(size_t)T_ROWS * DBOT];    // 8 MB fp8 bottleneck activations
__device__ unsigned char g_WdT[(size_t)DBOT * DIM];     // W_down^T * 64, fp8  [n][k]
__device__ unsigned char g_WuT[(size_t)DIM * DBOT];     // W_up^T   * 32, fp8  [n][k]

// ---------------------------------------------------------------------------
// PTX helpers
// ---------------------------------------------------------------------------
__device__ __forceinline__ unsigned smem_u32(const void* p) {
    return (unsigned)__cvta_generic_to_shared(p);
}
__device__ __forceinline__ void cpa16(unsigned dst, const void* src) {
    asm volatile("cp.async.cg.shared.global [%0], [%1], 16;\n" :: "r"(dst), "l"(src));
}
__device__ __forceinline__ void cpa_commit() {
    asm volatile("cp.async.commit_group;\n");
}
template <int N>
__device__ __forceinline__ void cpa_wait() {
    asm volatile("cp.async.wait_group %0;\n" :: "n"(N));
}
__device__ __forceinline__ void ldsm_x4(unsigned& r0, unsigned& r1, unsigned& r2, unsigned& r3,
                                        unsigned addr) {
    asm volatile("ldmatrix.sync.aligned.m8n8.x4.shared.b16 {%0,%1,%2,%3}, [%4];\n"
                 : "=r"(r0), "=r"(r1), "=r"(r2), "=r"(r3) : "r"(addr));
}
// FP8 e4m3 MMA: 16x8x32, fp32 accumulate
__device__ __forceinline__ void mma_f8(float c[4], const unsigned a[4], const unsigned b[2]) {
    asm volatile(
        "mma.sync.aligned.m16n8k32.row.col.f32.e4m3.e4m3.f32 "
        "{%0,%1,%2,%3}, {%4,%5,%6,%7}, {%8,%9}, {%0,%1,%2,%3};\n"
        : "+f"(c[0]), "+f"(c[1]), "+f"(c[2]), "+f"(c[3])
        : "r"(a[0]), "r"(a[1]), "r"(a[2]), "r"(a[3]), "r"(b[0]), "r"(b[1]));
}
__device__ __forceinline__ unsigned short pack_fp8x2(float lo, float hi) {
    unsigned short r;
    asm("cvt.rn.satfinite.e4m3x2.f32 %0, %1, %2;" : "=h"(r) : "f"(hi), "f"(lo));
    return r;
}
__device__ __forceinline__ unsigned pack_fp8x4(float a, float b, float c, float d) {
    unsigned short lo = pack_fp8x2(a, b);
    unsigned short hi = pack_fp8x2(c, d);
    return (unsigned)lo | ((unsigned)hi << 16);
}
__device__ __forceinline__ unsigned char f2fp8(float v) {
    return (unsigned char)pack_fp8x2(v, 0.f);
}
__device__ __forceinline__ float silu(float v) {
    return v * (1.f / (1.f + __expf(-v)));
}

// ---------------------------------------------------------------------------
// Fused LayerNorm -> fp8 h_norm
// ---------------------------------------------------------------------------
__global__ __launch_bounds__(256) void ln_norm_kernel(
    const float* __restrict__ hidden,
    const float* __restrict__ gamma,
    const float* __restrict__ beta)
{
    const int row = blockIdx.x;
    const int t = threadIdx.x;
    const int warp = t >> 5, lane = t & 31;

    const float4* hp = reinterpret_cast<const float4*>(hidden + (size_t)row * DIM);
    float4 v0 = hp[t], v1 = hp[t + 256];

    float s  = v0.x + v0.y + v0.z + v0.w + v1.x + v1.y + v1.z + v1.w;
    float ss = v0.x * v0.x + v0.y * v0.y + v0.z * v0.z + v0.w * v0.w
             + v1.x * v1.x + v1.y * v1.y + v1.z * v1.z + v1.w * v1.w;
#pragma unroll
    for (int o = 16; o > 0; o >>= 1) {
        s  += __shfl_xor_sync(0xffffffffu, s, o);
        ss += __shfl_xor_sync(0xffffffffu, ss, o);
    }
    __shared__ float rs[8], rss[8], stats[2];
    if (lane == 0) { rs[warp] = s; rss[warp] = ss; }
    __syncthreads();
    if (warp == 0) {
        float s2  = (lane < 8) ? rs[lane]  : 0.f;
        float ss2 = (lane < 8) ? rss[lane] : 0.f;
#pragma unroll
        for (int o = 4; o > 0; o >>= 1) {
            s2  += __shfl_xor_sync(0xffffffffu, s2, o);
            ss2 += __shfl_xor_sync(0xffffffffu, ss2, o);
        }
        if (lane == 0) {
            float mu  = s2 * (1.f / DIM);
            float var = ss2 * (1.f / DIM) - mu * mu;
            stats[0] = mu;
            stats[1] = rsqrtf(var + LN_EPS);
        }
    }
    __syncthreads();
    const float mu = stats[0], rstd = stats[1];

    const float4* gp = reinterpret_cast<const float4*>(gamma);
    const float4* bp = reinterpret_cast<const float4*>(beta);
    float4 g0 = gp[t], g1 = gp[t + 256];
    float4 b0 = bp[t], b1 = bp[t + 256];

    unsigned* dst = reinterpret_cast<unsigned*>(g_hn + (size_t)row * DIM);
    dst[t] = pack_fp8x4((v0.x - mu) * rstd * g0.x + b0.x,
                        (v0.y - mu) * rstd * g0.y + b0.y,
                        (v0.z - mu) * rstd * g0.z + b0.z,
                        (v0.w - mu) * rstd * g0.w + b0.w);
    dst[t + 256] = pack_fp8x4((v1.x - mu) * rstd * g1.x + b1.x,
                              (v1.y - mu) * rstd * g1.y + b1.y,
                              (v1.z - mu) * rstd * g1.z + b1.z,
                              (v1.w - mu) * rstd * g1.w + b1.w);
}

// ---------------------------------------------------------------------------
// fp32 [R][C] -> fp8 transposed [C][R], scaled
// ---------------------------------------------------------------------------
__global__ void transpose_fp8_kernel(const float* __restrict__ src, int R, int C,
                                     unsigned char* __restrict__ dst, float scale)
{
    __shared__ float tile[32][33];
    int x  = blockIdx.x * 32 + threadIdx.x;
    int y0 = blockIdx.y * 32;
#pragma unroll
    for (int j = 0; j < 32; j += 8)
        tile[threadIdx.y + j][threadIdx.x] = src[(size_t)(y0 + threadIdx.y + j) * C + x];
    __syncthreads();
    int xr  = blockIdx.y * 32 + threadIdx.x;
    int yc0 = blockIdx.x * 32;
#pragma unroll
    for (int j = 0; j < 32; j += 8)
        dst[(size_t)(yc0 + threadIdx.y + j) * R + xr] =
            f2fp8(tile[threadIdx.x][threadIdx.y + j] * scale);
}

// ---------------------------------------------------------------------------
// Shared FP8 GEMM mainloop: 4-stage cp.async pipeline, unrolled by 4 so
// every smem address is base+immediate; global pointers advance by +=KTB.
// ---------------------------------------------------------------------------
__device__ __forceinline__ void gemm_mainloop(
    const unsigned char* __restrict__ Ag, int ldaB,
    const unsigned char* __restrict__ Bg, int ldbB,
    int KBytes, int rowBase, int n0,
    unsigned sbase,
    float c[4][4][4])
{
    const int tid  = threadIdx.x;
    const int warp = tid >> 5, lane = tid & 31;
    const int wm = warp >> 2, wn = warp & 3;

    const int aRow     = ((lane >> 3) & 1) * 8 + (lane & 7);
    const int aColOffB = (lane >> 4) * 16;
    const int bRow     = (lane >> 4) * 8 + (lane & 7);
    const int bColOffB = ((lane >> 3) & 1) * 16;

    // warp-invariant fragment base addresses (slot 0, k-offset 0)
    unsigned aBase[4], bBase[2];
#pragma unroll
    for (int mi = 0; mi < 4; ++mi)
        aBase[mi] = sbase + (unsigned)((wm * 64 + mi * 16 + aRow) * BKB + aColOffB);
#pragma unroll
    for (int p = 0; p < 2; ++p)
        bBase[p] = sbase + (unsigned)(BM * BKB + (wn * 32 + p * 16 + bRow) * BKB + bColOffB);

    // per-thread load state: 2 A rows + 2 B rows, 16B each
    const int r0i = tid >> 2;
    const int ci  = (tid & 3) * 16;
    const unsigned dA0 = sbase + (unsigned)(r0i * BKB + ci);
    const unsigned dA1 = sbase + (unsigned)((r0i + 64) * BKB + ci);
    const unsigned dB0 = sbase + (unsigned)(BM * BKB + r0i * BKB + ci);
    const unsigned dB1 = sbase + (unsigned)(BM * BKB + (r0i + 64) * BKB + ci);
    const unsigned char* pA0 = Ag + (size_t)(rowBase + r0i) * ldaB + ci;
    const unsigned char* pA1 = pA0 + (size_t)64 * ldaB;
    const unsigned char* pB0 = Bg + (size_t)(n0 + r0i) * ldbB + ci;
    const unsigned char* pB1 = pB0 + (size_t)64 * ldbB;

    const int niter = KBytes / KTB;   // multiple of 4 for both GEMMs

    // prologue: tiles 0..2 -> slots 0..2
#pragma unroll
    for (int s = 0; s < 3; ++s) {
        const unsigned off = (unsigned)(s * STAGE_BYTES);
        cpa16(dA0 + off, pA0); cpa16(dA1 + off, pA1);
        cpa16(dB0 + off, pB0); cpa16(dB1 + off, pB1);
        cpa_commit();
        pA0 += KTB; pA1 += KTB; pB0 += KTB; pB1 += KTB;
    }

    for (int it4 = 0; it4 < niter; it4 += 4) {
#pragma unroll
        for (int u = 0; u < 4; ++u) {       // slot = u (compile-time)
            cpa_wait<2>();
            __syncthreads();

            if (it4 + u + 3 < niter) {
                const unsigned off = (unsigned)(((u + 3) & 3) * STAGE_BYTES);
                cpa16(dA0 + off, pA0); cpa16(dA1 + off, pA1);
                cpa16(dB0 + off, pB0); cpa16(dB1 + off, pB1);
                pA0 += KTB; pA1 += KTB; pB0 += KTB; pB1 += KTB;
            }
            cpa_commit();

            const unsigned soff = (unsigned)(u * STAGE_BYTES);
#pragma unroll
            for (int kkB = 0; kkB < KTB; kkB += 32) {    // one m16n8k32 step = 32 B of K
                unsigned a[4][4], b[4][2];
#pragma unroll
                for (int mi = 0; mi < 4; ++mi)
                    ldsm_x4(a[mi][0], a[mi][1], a[mi][2], a[mi][3],
                            aBase[mi] + (soff + (unsigned)kkB));
#pragma unroll
                for (int p = 0; p < 2; ++p)
                    ldsm_x4(b[2 * p][0], b[2 * p][1], b[2 * p + 1][0], b[2 * p + 1][1],
                            bBase[p] + (soff + (unsigned)kkB));
#pragma unroll
                for (int mi = 0; mi < 4; ++mi)
#pragma unroll
                    for (int ni = 0; ni < 4; ++ni)
                        mma_f8(c[mi][ni], a[mi], b[ni]);
            }
        }
    }
}

// ---------------------------------------------------------------------------
// GEMM1: z = SiLU( h_norm @ (W_down*64) / 64 + b_down )  -> fp8 g_z
// ---------------------------------------------------------------------------
__global__ __launch_bounds__(256, 2) void gemm1_kernel(const float* __restrict__ bd)
{
    extern __shared__ __align__(16) unsigned char smem[];

    const int tid  = threadIdx.x;
    const int warp = tid >> 5, lane = tid & 31;
    const int wm = warp >> 2, wn = warp & 3;
    const int group = lane >> 2, tg = lane & 3;
    const int rowBase = blockIdx.y * BM;
    const int n0      = blockIdx.x * BN;

    float c[4][4][4];
#pragma unroll
    for (int i = 0; i < 4; i++)
#pragma unroll
        for (int j = 0; j < 4; j++)
#pragma unroll
            for (int k = 0; k < 4; k++) c[i][j][k] = 0.f;

    gemm_mainloop(g_hn, DIM, g_WdT, DIM, DIM, rowBase, n0, smem_u32(smem), c);

    const float inv = 1.f / WD_SCALE;
#pragma unroll
    for (int mi = 0; mi < 4; ++mi) {
        int r0 = rowBase + wm * 64 + mi * 16 + group;
#pragma unroll
        for (int ni = 0; ni < 4; ++ni) {
            int cc = n0 + wn * 32 + ni * 8 + tg * 2;
            float bd0 = bd[cc], bd1 = bd[cc + 1];
            *reinterpret_cast<unsigned short*>(&g_z[(size_t)r0 * DBOT + cc]) =
                pack_fp8x2(silu(c[mi][ni][0] * inv + bd0), silu(c[mi][ni][1] * inv + bd1));
            *reinterpret_cast<unsigned short*>(&g_z[(size_t)(r0 + 8) * DBOT + cc]) =
                pack_fp8x2(silu(c[mi][ni][2] * inv + bd0), silu(c[mi][ni][3] * inv + bd1));
        }
    }
}

// ---------------------------------------------------------------------------
// GEMM2: out = hidden + alpha * ( z @ (W_up*32)/32 + b_up - hidden )
// ---------------------------------------------------------------------------
__global__ __launch_bounds__(256, 2) void gemm2_kernel(
    const float* __restrict__ hidden,
    const float* __restrict__ bu,
    const float* __restrict__ alpha_p,
    float* __restrict__ out)
{
    extern __shared__ __align__(16) unsigned char smem[];

    const int tid  = threadIdx.x;
    const int warp = tid >> 5, lane = tid & 31;
    const int wm = warp >> 2, wn = warp & 3;
    const int group = lane >> 2, tg = lane & 3;
    const int rowBase = blockIdx.y * BM;
    const int n0      = blockIdx.x * BN;

    float c[4][4][4];
#pragma unroll
    for (int i = 0; i < 4; i++)
#pragma unroll
        for (int j = 0; j < 4; j++)
#pragma unroll
            for (int k = 0; k < 4; k++) c[i][j][k] = 0.f;

    gemm_mainloop(g_z, DBOT, g_WuT, DBOT, DBOT, rowBase, n0, smem_u32(smem), c);

    const float al = alpha_p[0];
    const float inv = 1.f / WU_SCALE;
#pragma unroll
    for (int mi = 0; mi < 4; ++mi) {
        int r0 = rowBase + wm * 64 + mi * 16 + group;
        int r1 = r0 + 8;
#pragma unroll
        for (int ni = 0; ni < 4; ++ni) {
            int cc = n0 + wn * 32 + ni * 8 + tg * 2;
            float bu0 = bu[cc], bu1 = bu[cc + 1];

            float2 h0 = *reinterpret_cast<const float2*>(hidden + (size_t)r0 * DIM + cc);
            float2 h1 = *reinterpret_cast<const float2*>(hidden + (size_t)r1 * DIM + cc);

            float2 o0, o1;
            o0.x = h0.x + al * (c[mi][ni][0] * inv + bu0 - h0.x);
            o0.y = h0.y + al * (c[mi][ni][1] * inv + bu1 - h0.y);
            o1.x = h1.x + al * (c[mi][ni][2] * inv + bu0 - h1.x);
            o1.y = h1.y + al * (c[mi][ni][3] * inv + bu1 - h1.y);

            *reinterpret_cast<float2*>(out + (size_t)r0 * DIM + cc) = o0;
            *reinterpret_cast<float2*>(out + (size_t)r1 * DIM + cc) = o1;
        }
    }
}

// ---------------------------------------------------------------------------
// Launch
// ---------------------------------------------------------------------------
extern "C" void kernel_launch(void* const* d_in, const int* in_sizes, int n_in,
                              void* d_out, int out_size) {
    const float* hidden = (const float*)d_in[0];
    const float* gamma  = (const float*)d_in[1];
    const float* beta   = (const float*)d_in[2];
    const float* Wd     = (const float*)d_in[3];
    const float* bd     = (const float*)d_in[4];
    const float* Wu     = (const float*)d_in[5];
    const float* bu     = (const float*)d_in[6];
    const float* alpha  = (const float*)d_in[7];
    float* out = (float*)d_out;

    unsigned char *wdT, *wuT;
    cudaGetSymbolAddress((void**)&wdT, g_WdT);
    cudaGetSymbolAddress((void**)&wuT, g_WuT);

    cudaFuncSetAttribute(gemm1_kernel, cudaFuncAttributeMaxDynamicSharedMemorySize, DYN_BYTES);
    cudaFuncSetAttribute(gemm2_kernel, cudaFuncAttributeMaxDynamicSharedMemorySize, DYN_BYTES);

    dim3 tb(32, 8);
    transpose_fp8_kernel<<<dim3(DBOT / 32, DIM / 32), tb>>>(Wd, DIM, DBOT, wdT, WD_SCALE);
    transpose_fp8_kernel<<<dim3(DIM / 32, DBOT / 32), tb>>>(Wu, DBOT, DIM, wuT, WU_SCALE);
    ln_norm_kernel<<<T_ROWS, 256>>>(hidden, gamma, beta);
    gemm1_kernel<<<dim3(DBOT / BN, T_ROWS / BM), 256, DYN_BYTES>>>(bd);
    gemm2_kernel<<<dim3(DIM / BN, T_ROWS / BM), 256, DYN_BYTES>>>(hidden, bu, alpha, out);
}

// round 12
// speedup vs baseline: 3.4870x; 1.0938x over previous
#include <cuda_runtime.h>
#include <cuda_bf16.h>
#include <cstdint>

// Problem dims (fixed): B=4, S=4096, D=2048, Db=512
#define T_ROWS 16384
#define DIM    2048
#define DBOT   512
#define LN_EPS 1e-5f

// FP8 GEMM tiling (byte units; fp8 = 1 B/elt)
#define BM 64
#define BN 64
#define KTB 64                         // K bytes per tile (64 fp8 elements)
#define BKB 80                         // padded row stride bytes (16B-aligned cp.async, conflict-free)
#define STAGES 4
#define STAGE_BYTES ((BM + BN) * BKB)  // 10240
#define DYN_BYTES (STAGES * STAGE_BYTES)  // 40960
#define THREADS 128

#define WD_SCALE 64.f
#define WU_SCALE 32.f

// ---------------------------------------------------------------------------
// Device scratch (allocation forbidden -> __device__ globals)
// ---------------------------------------------------------------------------
__device__ unsigned char g_hn[(size_t)T_ROWS * DIM];    // 32 MB fp8 normalized hidden
__device__ unsigned char g_z[(size_t)T_ROWS * DBOT];    // 8 MB fp8 bottleneck activations
__device__ unsigned char g_WdT[(size_t)DBOT * DIM];     // W_down^T * 64, fp8  [n][k]
__device__ unsigned char g_WuT[(size_t)DIM * DBOT];     // W_up^T   * 32, fp8  [n][k]

// ---------------------------------------------------------------------------
// PTX helpers
// ---------------------------------------------------------------------------
__device__ __forceinline__ unsigned smem_u32(const void* p) {
    return (unsigned)__cvta_generic_to_shared(p);
}
__device__ __forceinline__ void cpa16(unsigned dst, const void* src) {
    asm volatile("cp.async.cg.shared.global [%0], [%1], 16;\n" :: "r"(dst), "l"(src));
}
__device__ __forceinline__ void cpa_commit() {
    asm volatile("cp.async.commit_group;\n");
}
template <int N>
__device__ __forceinline__ void cpa_wait() {
    asm volatile("cp.async.wait_group %0;\n" :: "n"(N));
}
__device__ __forceinline__ void ldsm_x4(unsigned& r0, unsigned& r1, unsigned& r2, unsigned& r3,
                                        unsigned addr) {
    asm volatile("ldmatrix.sync.aligned.m8n8.x4.shared.b16 {%0,%1,%2,%3}, [%4];\n"
                 : "=r"(r0), "=r"(r1), "=r"(r2), "=r"(r3) : "r"(addr));
}
// FP8 e4m3 MMA: 16x8x32, fp32 accumulate
__device__ __forceinline__ void mma_f8(float c[4], const unsigned a[4], const unsigned b[2]) {
    asm volatile(
        "mma.sync.aligned.m16n8k32.row.col.f32.e4m3.e4m3.f32 "
        "{%0,%1,%2,%3}, {%4,%5,%6,%7}, {%8,%9}, {%0,%1,%2,%3};\n"
        : "+f"(c[0]), "+f"(c[1]), "+f"(c[2]), "+f"(c[3])
        : "r"(a[0]), "r"(a[1]), "r"(a[2]), "r"(a[3]), "r"(b[0]), "r"(b[1]));
}
__device__ __forceinline__ unsigned short pack_fp8x2(float lo, float hi) {
    unsigned short r;
    asm("cvt.rn.satfinite.e4m3x2.f32 %0, %1, %2;" : "=h"(r) : "f"(hi), "f"(lo));
    return r;
}
__device__ __forceinline__ unsigned pack_fp8x4(float a, float b, float c, float d) {
    unsigned short lo = pack_fp8x2(a, b);
    unsigned short hi = pack_fp8x2(c, d);
    return (unsigned)lo | ((unsigned)hi << 16);
}
__device__ __forceinline__ unsigned char f2fp8(float v) {
    return (unsigned char)pack_fp8x2(v, 0.f);
}
__device__ __forceinline__ float silu(float v) {
    return v * (1.f / (1.f + __expf(-v)));
}

// ---------------------------------------------------------------------------
// Fused LayerNorm -> fp8 h_norm
// ---------------------------------------------------------------------------
__global__ __launch_bounds__(256) void ln_norm_kernel(
    const float* __restrict__ hidden,
    const float* __restrict__ gamma,
    const float* __restrict__ beta)
{
    const int row = blockIdx.x;
    const int t = threadIdx.x;
    const int warp = t >> 5, lane = t & 31;

    const float4* hp = reinterpret_cast<const float4*>(hidden + (size_t)row * DIM);
    float4 v0 = hp[t], v1 = hp[t + 256];

    float s  = v0.x + v0.y + v0.z + v0.w + v1.x + v1.y + v1.z + v1.w;
    float ss = v0.x * v0.x + v0.y * v0.y + v0.z * v0.z + v0.w * v0.w
             + v1.x * v1.x + v1.y * v1.y + v1.z * v1.z + v1.w * v1.w;
#pragma unroll
    for (int o = 16; o > 0; o >>= 1) {
        s  += __shfl_xor_sync(0xffffffffu, s, o);
        ss += __shfl_xor_sync(0xffffffffu, ss, o);
    }
    __shared__ float rs[8], rss[8], stats[2];
    if (lane == 0) { rs[warp] = s; rss[warp] = ss; }
    __syncthreads();
    if (warp == 0) {
        float s2  = (lane < 8) ? rs[lane]  : 0.f;
        float ss2 = (lane < 8) ? rss[lane] : 0.f;
#pragma unroll
        for (int o = 4; o > 0; o >>= 1) {
            s2  += __shfl_xor_sync(0xffffffffu, s2, o);
            ss2 += __shfl_xor_sync(0xffffffffu, ss2, o);
        }
        if (lane == 0) {
            float mu  = s2 * (1.f / DIM);
            float var = ss2 * (1.f / DIM) - mu * mu;
            stats[0] = mu;
            stats[1] = rsqrtf(var + LN_EPS);
        }
    }
    __syncthreads();
    const float mu = stats[0], rstd = stats[1];

    const float4* gp = reinterpret_cast<const float4*>(gamma);
    const float4* bp = reinterpret_cast<const float4*>(beta);
    float4 g0 = gp[t], g1 = gp[t + 256];
    float4 b0 = bp[t], b1 = bp[t + 256];

    unsigned* dst = reinterpret_cast<unsigned*>(g_hn + (size_t)row * DIM);
    dst[t] = pack_fp8x4((v0.x - mu) * rstd * g0.x + b0.x,
                        (v0.y - mu) * rstd * g0.y + b0.y,
                        (v0.z - mu) * rstd * g0.z + b0.z,
                        (v0.w - mu) * rstd * g0.w + b0.w);
    dst[t + 256] = pack_fp8x4((v1.x - mu) * rstd * g1.x + b1.x,
                              (v1.y - mu) * rstd * g1.y + b1.y,
                              (v1.z - mu) * rstd * g1.z + b1.z,
                              (v1.w - mu) * rstd * g1.w + b1.w);
}

// ---------------------------------------------------------------------------
// fp32 [R][C] -> fp8 transposed [C][R], scaled
// ---------------------------------------------------------------------------
__global__ void transpose_fp8_kernel(const float* __restrict__ src, int R, int C,
                                     unsigned char* __restrict__ dst, float scale)
{
    __shared__ float tile[32][33];
    int x  = blockIdx.x * 32 + threadIdx.x;
    int y0 = blockIdx.y * 32;
#pragma unroll
    for (int j = 0; j < 32; j += 8)
        tile[threadIdx.y + j][threadIdx.x] = src[(size_t)(y0 + threadIdx.y + j) * C + x];
    __syncthreads();
    int xr  = blockIdx.y * 32 + threadIdx.x;
    int yc0 = blockIdx.x * 32;
#pragma unroll
    for (int j = 0; j < 32; j += 8)
        dst[(size_t)(yc0 + threadIdx.y + j) * R + xr] =
            f2fp8(tile[threadIdx.x][threadIdx.y + j] * scale);
}

// ---------------------------------------------------------------------------
// FP8 GEMM mainloop: 64x64 CTA tile, 4 warps (warp tile 32x32), 4-stage
// cp.async pipeline unrolled by 4 (compile-time slots), one 128-thread
// __syncthreads per K-tile. 32 fp32 accumulators/thread -> no spills.
// ---------------------------------------------------------------------------
__device__ __forceinline__ void gemm_mainloop(
    const unsigned char* __restrict__ Ag, int ldaB,
    const unsigned char* __restrict__ Bg, int ldbB,
    int KBytes, int rowBase, int n0,
    unsigned sbase,
    float c[2][4][4])
{
    const int tid  = threadIdx.x;
    const int warp = tid >> 5, lane = tid & 31;
    const int wm = warp >> 1, wn = warp & 1;     // 2x2 warp grid, 32x32 tiles

    const int aRow     = ((lane >> 3) & 1) * 8 + (lane & 7);
    const int aColOffB = (lane >> 4) * 16;
    const int bRow     = (lane >> 4) * 8 + (lane & 7);
    const int bColOffB = ((lane >> 3) & 1) * 16;

    // warp-invariant fragment base addresses (slot 0, k-offset 0)
    unsigned aBase[2], bBase[2];
#pragma unroll
    for (int mi = 0; mi < 2; ++mi)
        aBase[mi] = sbase + (unsigned)((wm * 32 + mi * 16 + aRow) * BKB + aColOffB);
#pragma unroll
    for (int p = 0; p < 2; ++p)
        bBase[p] = sbase + (unsigned)(BM * BKB + (wn * 32 + p * 16 + bRow) * BKB + bColOffB);

    // per-thread load state: 2 A rows + 2 B rows, 16B each (64+64 rows x 64B)
    const int r0i = tid >> 2;            // 0..31
    const int ci  = (tid & 3) * 16;      // 0..48
    const unsigned dA0 = sbase + (unsigned)(r0i * BKB + ci);
    const unsigned dA1 = sbase + (unsigned)((r0i + 32) * BKB + ci);
    const unsigned dB0 = sbase + (unsigned)(BM * BKB + r0i * BKB + ci);
    const unsigned dB1 = sbase + (unsigned)(BM * BKB + (r0i + 32) * BKB + ci);
    const unsigned char* pA0 = Ag + (size_t)(rowBase + r0i) * ldaB + ci;
    const unsigned char* pA1 = pA0 + (size_t)32 * ldaB;
    const unsigned char* pB0 = Bg + (size_t)(n0 + r0i) * ldbB + ci;
    const unsigned char* pB1 = pB0 + (size_t)32 * ldbB;

    const int niter = KBytes / KTB;   // 32 (gemm1) / 8 (gemm2): multiples of 4

    // prologue: tiles 0..2 -> slots 0..2
#pragma unroll
    for (int s = 0; s < 3; ++s) {
        const unsigned off = (unsigned)(s * STAGE_BYTES);
        cpa16(dA0 + off, pA0); cpa16(dA1 + off, pA1);
        cpa16(dB0 + off, pB0); cpa16(dB1 + off, pB1);
        cpa_commit();
        pA0 += KTB; pA1 += KTB; pB0 += KTB; pB1 += KTB;
    }

    for (int it4 = 0; it4 < niter; it4 += 4) {
#pragma unroll
        for (int u = 0; u < 4; ++u) {       // slot = u (compile-time)
            cpa_wait<2>();
            __syncthreads();

            if (it4 + u + 3 < niter) {
                const unsigned off = (unsigned)(((u + 3) & 3) * STAGE_BYTES);
                cpa16(dA0 + off, pA0); cpa16(dA1 + off, pA1);
                cpa16(dB0 + off, pB0); cpa16(dB1 + off, pB1);
                pA0 += KTB; pA1 += KTB; pB0 += KTB; pB1 += KTB;
            }
            cpa_commit();

            const unsigned soff = (unsigned)(u * STAGE_BYTES);
#pragma unroll
            for (int kkB = 0; kkB < KTB; kkB += 32) {    // one m16n8k32 step = 32 B of K
                unsigned a[2][4], b[4][2];
#pragma unroll
                for (int mi = 0; mi < 2; ++mi)
                    ldsm_x4(a[mi][0], a[mi][1], a[mi][2], a[mi][3],
                            aBase[mi] + (soff + (unsigned)kkB));
#pragma unroll
                for (int p = 0; p < 2; ++p)
                    ldsm_x4(b[2 * p][0], b[2 * p][1], b[2 * p + 1][0], b[2 * p + 1][1],
                            bBase[p] + (soff + (unsigned)kkB));
#pragma unroll
                for (int mi = 0; mi < 2; ++mi)
#pragma unroll
                    for (int ni = 0; ni < 4; ++ni)
                        mma_f8(c[mi][ni], a[mi], b[ni]);
            }
        }
    }
}

// ---------------------------------------------------------------------------
// GEMM1: z = SiLU( h_norm @ (W_down*64) / 64 + b_down )  -> fp8 g_z
// ---------------------------------------------------------------------------
__global__ __launch_bounds__(THREADS, 5) void gemm1_kernel(const float* __restrict__ bd)
{
    extern __shared__ __align__(16) unsigned char smem[];

    const int tid  = threadIdx.x;
    const int warp = tid >> 5, lane = tid & 31;
    const int wm = warp >> 1, wn = warp & 1;
    const int group = lane >> 2, tg = lane & 3;
    const int rowBase = blockIdx.y * BM;
    const int n0      = blockIdx.x * BN;

    float c[2][4][4];
#pragma unroll
    for (int i = 0; i < 2; i++)
#pragma unroll
        for (int j = 0; j < 4; j++)
#pragma unroll
            for (int k = 0; k < 4; k++) c[i][j][k] = 0.f;

    gemm_mainloop(g_hn, DIM, g_WdT, DIM, DIM, rowBase, n0, smem_u32(smem), c);

    const float inv = 1.f / WD_SCALE;
#pragma unroll
    for (int mi = 0; mi < 2; ++mi) {
        int r0 = rowBase + wm * 32 + mi * 16 + group;
#pragma unroll
        for (int ni = 0; ni < 4; ++ni) {
            int cc = n0 + wn * 32 + ni * 8 + tg * 2;
            float bd0 = bd[cc], bd1 = bd[cc + 1];
            *reinterpret_cast<unsigned short*>(&g_z[(size_t)r0 * DBOT + cc]) =
                pack_fp8x2(silu(c[mi][ni][0] * inv + bd0), silu(c[mi][ni][1] * inv + bd1));
            *reinterpret_cast<unsigned short*>(&g_z[(size_t)(r0 + 8) * DBOT + cc]) =
                pack_fp8x2(silu(c[mi][ni][2] * inv + bd0), silu(c[mi][ni][3] * inv + bd1));
        }
    }
}

// ---------------------------------------------------------------------------
// GEMM2: out = hidden + alpha * ( z @ (W_up*32)/32 + b_up - hidden )
// ---------------------------------------------------------------------------
__global__ __launch_bounds__(THREADS, 5) void gemm2_kernel(
    const float* __restrict__ hidden,
    const float* __restrict__ bu,
    const float* __restrict__ alpha_p,
    float* __restrict__ out)
{
    extern __shared__ __align__(16) unsigned char smem[];

    const int tid  = threadIdx.x;
    const int warp = tid >> 5, lane = tid & 31;
    const int wm = warp >> 1, wn = warp & 1;
    const int group = lane >> 2, tg = lane & 3;
    const int rowBase = blockIdx.y * BM;
    const int n0      = blockIdx.x * BN;

    float c[2][4][4];
#pragma unroll
    for (int i = 0; i < 2; i++)
#pragma unroll
        for (int j = 0; j < 4; j++)
#pragma unroll
            for (int k = 0; k < 4; k++) c[i][j][k] = 0.f;

    gemm_mainloop(g_z, DBOT, g_WuT, DBOT, DBOT, rowBase, n0, smem_u32(smem), c);

    const float al = alpha_p[0];
    const float inv = 1.f / WU_SCALE;
#pragma unroll
    for (int mi = 0; mi < 2; ++mi) {
        int r0 = rowBase + wm * 32 + mi * 16 + group;
        int r1 = r0 + 8;
#pragma unroll
        for (int ni = 0; ni < 4; ++ni) {
            int cc = n0 + wn * 32 + ni * 8 + tg * 2;
            float bu0 = bu[cc], bu1 = bu[cc + 1];

            float2 h0 = *reinterpret_cast<const float2*>(hidden + (size_t)r0 * DIM + cc);
            float2 h1 = *reinterpret_cast<const float2*>(hidden + (size_t)r1 * DIM + cc);

            float2 o0, o1;
            o0.x = h0.x + al * (c[mi][ni][0] * inv + bu0 - h0.x);
            o0.y = h0.y + al * (c[mi][ni][1] * inv + bu1 - h0.y);
            o1.x = h1.x + al * (c[mi][ni][2] * inv + bu0 - h1.x);
            o1.y = h1.y + al * (c[mi][ni][3] * inv + bu1 - h1.y);

            *reinterpret_cast<float2*>(out + (size_t)r0 * DIM + cc) = o0;
            *reinterpret_cast<float2*>(out + (size_t)r1 * DIM + cc) = o1;
        }
    }
}

// ---------------------------------------------------------------------------
// Launch
// ---------------------------------------------------------------------------
extern "C" void kernel_launch(void* const* d_in, const int* in_sizes, int n_in,
                              void* d_out, int out_size) {
    const float* hidden = (const float*)d_in[0];
    const float* gamma  = (const float*)d_in[1];
    const float* beta   = (const float*)d_in[2];
    const float* Wd     = (const float*)d_in[3];
    const float* bd     = (const float*)d_in[4];
    const float* Wu     = (const float*)d_in[5];
    const float* bu     = (const float*)d_in[6];
    const float* alpha  = (const float*)d_in[7];
    float* out = (float*)d_out;

    unsigned char *wdT, *wuT;
    cudaGetSymbolAddress((void**)&wdT, g_WdT);
    cudaGetSymbolAddress((void**)&wuT, g_WuT);

    cudaFuncSetAttribute(gemm1_kernel, cudaFuncAttributeMaxDynamicSharedMemorySize, DYN_BYTES);
    cudaFuncSetAttribute(gemm2_kernel, cudaFuncAttributeMaxDynamicSharedMemorySize, DYN_BYTES);

    dim3 tb(32, 8);
    transpose_fp8_kernel<<<dim3(DBOT / 32, DIM / 32), tb>>>(Wd, DIM, DBOT, wdT, WD_SCALE);
    transpose_fp8_kernel<<<dim3(DIM / 32, DBOT / 32), tb>>>(Wu, DBOT, DIM, wuT, WU_SCALE);
    ln_norm_kernel<<<T_ROWS, 256>>>(hidden, gamma, beta);
    gemm1_kernel<<<dim3(DBOT / BN, T_ROWS / BM), THREADS, DYN_BYTES>>>(bd);
    gemm2_kernel<<<dim3(DIM / BN, T_ROWS / BM), THREADS, DYN_BYTES>>>(hidden, bu, alpha, out);
}